// round 8
// baseline (speedup 1.0000x reference)
#include <cuda_runtime.h>
#include <cuda_bf16.h>
#include <math.h>
#include <stdint.h>

#define BB 2
#define SS 2048
#define DD 768
#define HH 12
#define DH 64
#define MM (BB*SS)

// scratch (no allocations allowed — __device__ globals are the sanctioned path)
__device__ float g_q[MM*DD];
__device__ float g_k[MM*DD];
__device__ float g_v[MM*DD];
__device__ float g_ctx[MM*DD];

__device__ __forceinline__ float to_tf32(float x) {
    float y;
    asm("cvt.rna.tf32.f32 %0, %1;" : "=f"(y) : "f"(x));
    return y;
}

__device__ __forceinline__ void mma_tf32(float* d,
                                         const uint32_t* a,
                                         const uint32_t* b) {
    asm volatile(
        "mma.sync.aligned.m16n8k8.row.col.f32.tf32.tf32.f32 "
        "{%0,%1,%2,%3}, {%4,%5,%6,%7}, {%8,%9}, {%0,%1,%2,%3};"
        : "+f"(d[0]), "+f"(d[1]), "+f"(d[2]), "+f"(d[3])
        : "r"(a[0]), "r"(a[1]), "r"(a[2]), "r"(a[3]),
          "r"(b[0]), "r"(b[1]));
}

__device__ __forceinline__ void mma_bf16(float* d,
                                         const uint32_t* a,
                                         const uint32_t* b) {
    asm volatile(
        "mma.sync.aligned.m16n8k16.row.col.f32.bf16.bf16.f32 "
        "{%0,%1,%2,%3}, {%4,%5,%6,%7}, {%8,%9}, {%0,%1,%2,%3};"
        : "+f"(d[0]), "+f"(d[1]), "+f"(d[2]), "+f"(d[3])
        : "r"(a[0]), "r"(a[1]), "r"(a[2]), "r"(a[3]),
          "r"(b[0]), "r"(b[1]));
}

// split (a,b) into packed bf16 hi-pair and lo-pair (low half = first element)
__device__ __forceinline__ void split2(float a, float b,
                                       uint32_t& hi, uint32_t& lo) {
    __nv_bfloat16 ah = __float2bfloat16(a);
    __nv_bfloat16 bh = __float2bfloat16(b);
    __nv_bfloat16 al = __float2bfloat16(a - __bfloat162float(ah));
    __nv_bfloat16 bl = __float2bfloat16(b - __bfloat162float(bh));
    hi = (uint32_t)__bfloat16_as_ushort(ah) |
         ((uint32_t)__bfloat16_as_ushort(bh) << 16);
    lo = (uint32_t)__bfloat16_as_ushort(al) |
         ((uint32_t)__bfloat16_as_ushort(bl) << 16);
}

// ---------------------------------------------------------------------------
// 3xTF32 mma.sync GEMM: C[M,768] = A[M,768] @ W[768,768] + bias  (unchanged)
// ---------------------------------------------------------------------------
#define ASTR 20
#define BSTR 132

__global__ void __launch_bounds__(256)
gemm_tf32_kernel(const float* __restrict__ A, const float* __restrict__ W,
                 const float* __restrict__ bias, float* __restrict__ C)
{
    __shared__ float AsH[128 * ASTR];
    __shared__ float AsL[128 * ASTR];
    __shared__ float BsH[16 * BSTR];
    __shared__ float BsL[16 * BSTR];
    __shared__ float sbias[128];

    const int tid  = threadIdx.x;
    const int warp = tid >> 5;
    const int lane = tid & 31;
    const int wm   = warp >> 2;
    const int wn   = warp & 3;
    const int m0   = blockIdx.y * 128;
    const int n0   = blockIdx.x * 128;

    if (tid < 128) sbias[tid] = bias[n0 + tid];

    const int ar0 = tid >> 2;
    const int ak0 = (tid & 3) << 2;
    const int ar1 = (tid + 256) >> 2;
    const int ak1 = ((tid + 256) & 3) << 2;
    const int bk0 = tid >> 5;
    const int bn0q = (tid & 31) << 2;
    const int bk1 = (tid + 256) >> 5;
    const int bn1q = ((tid + 256) & 31) << 2;

    float acc[4][4][4];
#pragma unroll
    for (int i = 0; i < 4; i++)
#pragma unroll
        for (int j = 0; j < 4; j++)
#pragma unroll
            for (int q = 0; q < 4; q++) acc[i][j][q] = 0.0f;

    float4 ra0, ra1, rb0, rb1;

    ra0 = *reinterpret_cast<const float4*>(&A[(long)(m0 + ar0) * DD + ak0]);
    ra1 = *reinterpret_cast<const float4*>(&A[(long)(m0 + ar1) * DD + ak1]);
    rb0 = *reinterpret_cast<const float4*>(&W[(long)bk0 * DD + n0 + bn0q]);
    rb1 = *reinterpret_cast<const float4*>(&W[(long)bk1 * DD + n0 + bn1q]);

#define SPLIT4(v, H, L, off) do {                                            \
    float4 _h, _l;                                                           \
    _h.x = to_tf32((v).x); _l.x = to_tf32((v).x - _h.x);                     \
    _h.y = to_tf32((v).y); _l.y = to_tf32((v).y - _h.y);                     \
    _h.z = to_tf32((v).z); _l.z = to_tf32((v).z - _h.z);                     \
    _h.w = to_tf32((v).w); _l.w = to_tf32((v).w - _h.w);                     \
    *reinterpret_cast<float4*>(&(H)[off]) = _h;                              \
    *reinterpret_cast<float4*>(&(L)[off]) = _l;                              \
} while (0)

#define STORE_TILES() do {                                                   \
    SPLIT4(ra0, AsH, AsL, ar0 * ASTR + ak0);                                 \
    SPLIT4(ra1, AsH, AsL, ar1 * ASTR + ak1);                                 \
    SPLIT4(rb0, BsH, BsL, bk0 * BSTR + bn0q);                                \
    SPLIT4(rb1, BsH, BsL, bk1 * BSTR + bn1q);                                \
} while (0)

    STORE_TILES();
    __syncthreads();

    const int NITER = DD / 16;
    for (int it = 0; it < NITER; it++) {
        if (it + 1 < NITER) {
            const int k0 = (it + 1) * 16;
            ra0 = *reinterpret_cast<const float4*>(&A[(long)(m0 + ar0) * DD + k0 + ak0]);
            ra1 = *reinterpret_cast<const float4*>(&A[(long)(m0 + ar1) * DD + k0 + ak1]);
            rb0 = *reinterpret_cast<const float4*>(&W[(long)(k0 + bk0) * DD + n0 + bn0q]);
            rb1 = *reinterpret_cast<const float4*>(&W[(long)(k0 + bk1) * DD + n0 + bn1q]);
        }

#pragma unroll
        for (int ks = 0; ks < 16; ks += 8) {
            uint32_t afH[4][4], afL[4][4], bfH[4][2], bfL[4][2];
            const int kk = ks + (lane & 3);
            const int rr = (lane >> 2);
#pragma unroll
            for (int mi = 0; mi < 4; mi++) {
                const int r = wm * 64 + mi * 16 + rr;
                afH[mi][0] = __float_as_uint(AsH[r * ASTR + kk]);
                afH[mi][1] = __float_as_uint(AsH[(r + 8) * ASTR + kk]);
                afH[mi][2] = __float_as_uint(AsH[r * ASTR + kk + 4]);
                afH[mi][3] = __float_as_uint(AsH[(r + 8) * ASTR + kk + 4]);
                afL[mi][0] = __float_as_uint(AsL[r * ASTR + kk]);
                afL[mi][1] = __float_as_uint(AsL[(r + 8) * ASTR + kk]);
                afL[mi][2] = __float_as_uint(AsL[r * ASTR + kk + 4]);
                afL[mi][3] = __float_as_uint(AsL[(r + 8) * ASTR + kk + 4]);
            }
#pragma unroll
            for (int ni = 0; ni < 4; ni++) {
                const int c = wn * 32 + ni * 8 + rr;
                bfH[ni][0] = __float_as_uint(BsH[kk * BSTR + c]);
                bfH[ni][1] = __float_as_uint(BsH[(kk + 4) * BSTR + c]);
                bfL[ni][0] = __float_as_uint(BsL[kk * BSTR + c]);
                bfL[ni][1] = __float_as_uint(BsL[(kk + 4) * BSTR + c]);
            }
#pragma unroll
            for (int mi = 0; mi < 4; mi++)
#pragma unroll
                for (int ni = 0; ni < 4; ni++) {
                    mma_tf32(acc[mi][ni], afH[mi], bfL[ni]);
                    mma_tf32(acc[mi][ni], afL[mi], bfH[ni]);
                    mma_tf32(acc[mi][ni], afH[mi], bfH[ni]);
                }
        }
        __syncthreads();
        if (it + 1 < NITER) {
            STORE_TILES();
            __syncthreads();
        }
    }

    const int rr = lane >> 2;
    const int cc = (lane & 3) * 2;
#pragma unroll
    for (int mi = 0; mi < 4; mi++) {
#pragma unroll
        for (int ni = 0; ni < 4; ni++) {
            const int col = wn * 32 + ni * 8 + cc;
            const int row = m0 + wm * 64 + mi * 16 + rr;
            float2 o0, o1;
            o0.x = acc[mi][ni][0] + sbias[col];
            o0.y = acc[mi][ni][1] + sbias[col + 1];
            o1.x = acc[mi][ni][2] + sbias[col];
            o1.y = acc[mi][ni][3] + sbias[col + 1];
            *reinterpret_cast<float2*>(&C[(long)row * DD + n0 + col]) = o0;
            *reinterpret_cast<float2*>(&C[(long)(row + 8) * DD + n0 + col]) = o1;
        }
    }
}

// ---------------------------------------------------------------------------
// Flash attention on tensor cores: bf16x3 mma.sync (m16n8k16), fp32 softmax.
// Per CTA: one (b,h), 64 queries, 8 warps (4 m-strips x 2 n-halves).
// Packed bf16 hi/lo tiles in smem; u32 row stride 33 (conflict-free).
// ---------------------------------------------------------------------------
#define PSTR 33
#define ATT_SMEM (8 * 64 * PSTR * 4 + 64 * 65 * 4 + 3 * 64 * 4)  // 84992

__global__ void __launch_bounds__(256)
attn_kernel()
{
    extern __shared__ char smraw[];
    uint32_t* Qh = reinterpret_cast<uint32_t*>(smraw);
    uint32_t* Ql = Qh + 64 * PSTR;
    uint32_t* Kh = Ql + 64 * PSTR;
    uint32_t* Kl = Kh + 64 * PSTR;
    uint32_t* Vh = Kl + 64 * PSTR;
    uint32_t* Vl = Vh + 64 * PSTR;
    uint32_t* Ph = Vl + 64 * PSTR;
    uint32_t* Pl = Ph + 64 * PSTR;
    float* Ss   = reinterpret_cast<float*>(Pl + 64 * PSTR);
    float* mrow = Ss + 64 * 65;
    float* lrow = mrow + 64;
    float* frow = lrow + 64;

    const int tid  = threadIdx.x;
    const int warp = tid >> 5;
    const int lane = tid & 31;
    const int g    = lane >> 2;
    const int tg   = lane & 3;
    const int wm   = (warp >> 1) * 16;   // m strip
    const int wn   = (warp & 1) * 32;    // n half
    const int bh   = blockIdx.y;
    const int b    = bh / HH;
    const int h    = bh % HH;
    const int q0   = blockIdx.x * 64;

    // load Q tile (packed hi/lo pairs along d)
    for (int idx = tid; idx < 64 * 32; idx += 256) {
        const int r = idx >> 5, kp = idx & 31;
        float2 v = *reinterpret_cast<const float2*>(
            &g_q[(long)(b * SS + q0 + r) * DD + h * DH + 2 * kp]);
        split2(v.x, v.y, Qh[r * PSTR + kp], Ql[r * PSTR + kp]);
    }
    if (tid < 64) { mrow[tid] = -INFINITY; lrow[tid] = 0.0f; }

    float o[4][4] = {};
    __syncthreads();

    for (int kt = 0; kt < SS / 64; kt++) {
        const int k0 = kt * 64;
        // K tile: rows = key idx, packed pairs along d
        for (int idx = tid; idx < 64 * 32; idx += 256) {
            const int r = idx >> 5, kp = idx & 31;
            float2 v = *reinterpret_cast<const float2*>(
                &g_k[(long)(b * SS + k0 + r) * DD + h * DH + 2 * kp]);
            split2(v.x, v.y, Kh[r * PSTR + kp], Kl[r * PSTR + kp]);
        }
        // V tile transposed: Vh[d][kpair] = {V[k0+2kp][d], V[k0+2kp+1][d]}
        for (int idx = tid; idx < 64 * 32; idx += 256) {
            const int d = idx & 63, kp = idx >> 6;
            const float v0 = g_v[(long)(b * SS + k0 + 2 * kp) * DD + h * DH + d];
            const float v1 = g_v[(long)(b * SS + k0 + 2 * kp + 1) * DD + h * DH + d];
            split2(v0, v1, Vh[d * PSTR + kp], Vl[d * PSTR + kp]);
        }
        __syncthreads();

        // S = Q @ K^T  (bf16x3)
        float sacc[4][4] = {};
        {
            const int r = wm + g;
#pragma unroll
            for (int ks = 0; ks < 4; ks++) {
                const int co = ks * 8;
                uint32_t aH[4], aL[4];
                aH[0] = Qh[r * PSTR + co + tg];
                aH[1] = Qh[(r + 8) * PSTR + co + tg];
                aH[2] = Qh[r * PSTR + co + tg + 4];
                aH[3] = Qh[(r + 8) * PSTR + co + tg + 4];
                aL[0] = Ql[r * PSTR + co + tg];
                aL[1] = Ql[(r + 8) * PSTR + co + tg];
                aL[2] = Ql[r * PSTR + co + tg + 4];
                aL[3] = Ql[(r + 8) * PSTR + co + tg + 4];
#pragma unroll
                for (int nt = 0; nt < 4; nt++) {
                    const int n = wn + nt * 8 + g;
                    uint32_t bH[2] = { Kh[n * PSTR + co + tg], Kh[n * PSTR + co + tg + 4] };
                    uint32_t bL[2] = { Kl[n * PSTR + co + tg], Kl[n * PSTR + co + tg + 4] };
                    mma_bf16(sacc[nt], aH, bL);
                    mma_bf16(sacc[nt], aL, bH);
                    mma_bf16(sacc[nt], aH, bH);
                }
            }
            // spill S fragments to smem
#pragma unroll
            for (int nt = 0; nt < 4; nt++) {
                const int c = wn + nt * 8 + 2 * tg;
                Ss[r * 65 + c]           = sacc[nt][0];
                Ss[r * 65 + c + 1]       = sacc[nt][1];
                Ss[(r + 8) * 65 + c]     = sacc[nt][2];
                Ss[(r + 8) * 65 + c + 1] = sacc[nt][3];
            }
        }
        __syncthreads();

        // parallel online softmax: 16 threads per row; emit packed bf16 P hi/lo
        {
            const int r0s = (tid >> 4) * 4;
            const int c0s = (tid & 15) * 4;
#pragma unroll
            for (int i = 0; i < 4; i++) {
                const int r = r0s + i;
                const float s0 = Ss[r * 65 + c0s];
                const float s1 = Ss[r * 65 + c0s + 1];
                const float s2 = Ss[r * 65 + c0s + 2];
                const float s3 = Ss[r * 65 + c0s + 3];
                float mi = fmaxf(fmaxf(s0, s1), fmaxf(s2, s3));
#pragma unroll
                for (int off = 1; off < 16; off <<= 1)
                    mi = fmaxf(mi, __shfl_xor_sync(0xffffffffu, mi, off));
                const float mold = mrow[r];
                const float mx   = fmaxf(mold, mi);
                const float p0 = __expf(s0 - mx);
                const float p1 = __expf(s1 - mx);
                const float p2 = __expf(s2 - mx);
                const float p3 = __expf(s3 - mx);
                float s = p0 + p1 + p2 + p3;
#pragma unroll
                for (int off = 1; off < 16; off <<= 1)
                    s += __shfl_xor_sync(0xffffffffu, s, off);
                uint32_t h0, l0, h1, l1;
                split2(p0, p1, h0, l0);
                split2(p2, p3, h1, l1);
                const int kp = c0s >> 1;
                Ph[r * PSTR + kp]     = h0;
                Ph[r * PSTR + kp + 1] = h1;
                Pl[r * PSTR + kp]     = l0;
                Pl[r * PSTR + kp + 1] = l1;
                if ((tid & 15) == 0) {
                    const float fr = __expf(mold - mx);
                    frow[r] = fr;
                    lrow[r] = lrow[r] * fr + s;
                    mrow[r] = mx;
                }
            }
        }
        __syncthreads();

        // O = O * f + P @ V  (bf16x3)
        {
            const int r = wm + g;
            const float fr0 = frow[r], fr1 = frow[r + 8];
#pragma unroll
            for (int nt = 0; nt < 4; nt++) {
                o[nt][0] *= fr0; o[nt][1] *= fr0;
                o[nt][2] *= fr1; o[nt][3] *= fr1;
            }
#pragma unroll
            for (int ks = 0; ks < 4; ks++) {
                const int co = ks * 8;
                uint32_t aH[4], aL[4];
                aH[0] = Ph[r * PSTR + co + tg];
                aH[1] = Ph[(r + 8) * PSTR + co + tg];
                aH[2] = Ph[r * PSTR + co + tg + 4];
                aH[3] = Ph[(r + 8) * PSTR + co + tg + 4];
                aL[0] = Pl[r * PSTR + co + tg];
                aL[1] = Pl[(r + 8) * PSTR + co + tg];
                aL[2] = Pl[r * PSTR + co + tg + 4];
                aL[3] = Pl[(r + 8) * PSTR + co + tg + 4];
#pragma unroll
                for (int nt = 0; nt < 4; nt++) {
                    const int d = wn + nt * 8 + g;
                    uint32_t bH[2] = { Vh[d * PSTR + co + tg], Vh[d * PSTR + co + tg + 4] };
                    uint32_t bL[2] = { Vl[d * PSTR + co + tg], Vl[d * PSTR + co + tg + 4] };
                    mma_bf16(o[nt], aH, bL);
                    mma_bf16(o[nt], aL, bH);
                    mma_bf16(o[nt], aH, bH);
                }
            }
        }
        __syncthreads();
    }

    // normalize and write ctx
    {
        const int r = wm + g;
        const float i0 = 1.0f / lrow[r];
        const float i1 = 1.0f / lrow[r + 8];
#pragma unroll
        for (int nt = 0; nt < 4; nt++) {
            const int dcol = h * DH + wn + nt * 8 + 2 * tg;
            float2 w0, w1;
            w0.x = o[nt][0] * i0; w0.y = o[nt][1] * i0;
            w1.x = o[nt][2] * i1; w1.y = o[nt][3] * i1;
            *reinterpret_cast<float2*>(&g_ctx[(long)(b * SS + q0 + r) * DD + dcol]) = w0;
            *reinterpret_cast<float2*>(&g_ctx[(long)(b * SS + q0 + r + 8) * DD + dcol]) = w1;
        }
    }
}

// ---------------------------------------------------------------------------
// Launch
// ---------------------------------------------------------------------------
extern "C" void kernel_launch(void* const* d_in, const int* in_sizes, int n_in,
                              void* d_out, int out_size)
{
    const float* x  = (const float*)d_in[0];
    const float* Wq = (const float*)d_in[1];
    const float* bq = (const float*)d_in[2];
    const float* Wk = (const float*)d_in[3];
    const float* bk = (const float*)d_in[4];
    const float* Wv = (const float*)d_in[5];
    const float* bv = (const float*)d_in[6];
    const float* Wo = (const float*)d_in[7];
    const float* bo = (const float*)d_in[8];
    float* out = (float*)d_out;

    void *pq, *pk, *pv, *pctx;
    cudaGetSymbolAddress(&pq,   g_q);
    cudaGetSymbolAddress(&pk,   g_k);
    cudaGetSymbolAddress(&pv,   g_v);
    cudaGetSymbolAddress(&pctx, g_ctx);

    cudaFuncSetAttribute(attn_kernel,
                         cudaFuncAttributeMaxDynamicSharedMemorySize, ATT_SMEM);

    dim3 ggrid(DD / 128, MM / 128);   // (6, 32)

    gemm_tf32_kernel<<<ggrid, 256>>>(x, Wq, bq, (float*)pq);
    gemm_tf32_kernel<<<ggrid, 256>>>(x, Wk, bk, (float*)pk);
    gemm_tf32_kernel<<<ggrid, 256>>>(x, Wv, bv, (float*)pv);

    dim3 agrid(SS / 64, BB * HH);     // (32, 24)
    attn_kernel<<<agrid, dim3(256), ATT_SMEM>>>();

    gemm_tf32_kernel<<<ggrid, 256>>>((const float*)pctx, Wo, bo, out);
}

// round 9
// speedup vs baseline: 1.2754x; 1.2754x over previous
#include <cuda_runtime.h>
#include <cuda_bf16.h>
#include <math.h>
#include <stdint.h>

#define BB 2
#define SS 2048
#define DD 768
#define HH 12
#define DH 64
#define MM (BB*SS)
#define DP (DD/2)     // 384 u32 pairs per row

// scratch (no allocations allowed — __device__ globals are the sanctioned path)
__device__ float g_q[MM*DD];
__device__ float g_k[MM*DD];
__device__ float g_v[MM*DD];
__device__ float g_ctx[MM*DD];
// packed bf16 hi/lo splits (pre-pass output)
__device__ uint32_t g_qh[MM*DP];
__device__ uint32_t g_ql[MM*DP];
__device__ uint32_t g_kh[MM*DP];
__device__ uint32_t g_kl[MM*DP];
__device__ uint32_t g_vth[MM*DP];   // V transposed: [(b*HH+h)*1024 + kp][d]
__device__ uint32_t g_vtl[MM*DP];

__device__ __forceinline__ float to_tf32(float x) {
    float y;
    asm("cvt.rna.tf32.f32 %0, %1;" : "=f"(y) : "f"(x));
    return y;
}

__device__ __forceinline__ void mma_tf32(float* d,
                                         const uint32_t* a,
                                         const uint32_t* b) {
    asm volatile(
        "mma.sync.aligned.m16n8k8.row.col.f32.tf32.tf32.f32 "
        "{%0,%1,%2,%3}, {%4,%5,%6,%7}, {%8,%9}, {%0,%1,%2,%3};"
        : "+f"(d[0]), "+f"(d[1]), "+f"(d[2]), "+f"(d[3])
        : "r"(a[0]), "r"(a[1]), "r"(a[2]), "r"(a[3]),
          "r"(b[0]), "r"(b[1]));
}

__device__ __forceinline__ void mma_bf16(float* d,
                                         const uint32_t* a,
                                         const uint32_t* b) {
    asm volatile(
        "mma.sync.aligned.m16n8k16.row.col.f32.bf16.bf16.f32 "
        "{%0,%1,%2,%3}, {%4,%5,%6,%7}, {%8,%9}, {%0,%1,%2,%3};"
        : "+f"(d[0]), "+f"(d[1]), "+f"(d[2]), "+f"(d[3])
        : "r"(a[0]), "r"(a[1]), "r"(a[2]), "r"(a[3]),
          "r"(b[0]), "r"(b[1]));
}

__device__ __forceinline__ void split2(float a, float b,
                                       uint32_t& hi, uint32_t& lo) {
    __nv_bfloat16 ah = __float2bfloat16(a);
    __nv_bfloat16 bh = __float2bfloat16(b);
    __nv_bfloat16 al = __float2bfloat16(a - __bfloat162float(ah));
    __nv_bfloat16 bl = __float2bfloat16(b - __bfloat162float(bh));
    hi = (uint32_t)__bfloat16_as_ushort(ah) |
         ((uint32_t)__bfloat16_as_ushort(bh) << 16);
    lo = (uint32_t)__bfloat16_as_ushort(al) |
         ((uint32_t)__bfloat16_as_ushort(bl) << 16);
}

// ---------------------------------------------------------------------------
// 3xTF32 mma.sync GEMM (unchanged)
// ---------------------------------------------------------------------------
#define ASTR 20
#define BSTR 132

__global__ void __launch_bounds__(256)
gemm_tf32_kernel(const float* __restrict__ A, const float* __restrict__ W,
                 const float* __restrict__ bias, float* __restrict__ C)
{
    __shared__ float AsH[128 * ASTR];
    __shared__ float AsL[128 * ASTR];
    __shared__ float BsH[16 * BSTR];
    __shared__ float BsL[16 * BSTR];
    __shared__ float sbias[128];

    const int tid  = threadIdx.x;
    const int warp = tid >> 5;
    const int lane = tid & 31;
    const int wm   = warp >> 2;
    const int wn   = warp & 3;
    const int m0   = blockIdx.y * 128;
    const int n0   = blockIdx.x * 128;

    if (tid < 128) sbias[tid] = bias[n0 + tid];

    const int ar0 = tid >> 2;
    const int ak0 = (tid & 3) << 2;
    const int ar1 = (tid + 256) >> 2;
    const int ak1 = ((tid + 256) & 3) << 2;
    const int bk0 = tid >> 5;
    const int bn0q = (tid & 31) << 2;
    const int bk1 = (tid + 256) >> 5;
    const int bn1q = ((tid + 256) & 31) << 2;

    float acc[4][4][4];
#pragma unroll
    for (int i = 0; i < 4; i++)
#pragma unroll
        for (int j = 0; j < 4; j++)
#pragma unroll
            for (int q = 0; q < 4; q++) acc[i][j][q] = 0.0f;

    float4 ra0, ra1, rb0, rb1;

    ra0 = *reinterpret_cast<const float4*>(&A[(long)(m0 + ar0) * DD + ak0]);
    ra1 = *reinterpret_cast<const float4*>(&A[(long)(m0 + ar1) * DD + ak1]);
    rb0 = *reinterpret_cast<const float4*>(&W[(long)bk0 * DD + n0 + bn0q]);
    rb1 = *reinterpret_cast<const float4*>(&W[(long)bk1 * DD + n0 + bn1q]);

#define SPLIT4(v, H, L, off) do {                                            \
    float4 _h, _l;                                                           \
    _h.x = to_tf32((v).x); _l.x = to_tf32((v).x - _h.x);                     \
    _h.y = to_tf32((v).y); _l.y = to_tf32((v).y - _h.y);                     \
    _h.z = to_tf32((v).z); _l.z = to_tf32((v).z - _h.z);                     \
    _h.w = to_tf32((v).w); _l.w = to_tf32((v).w - _h.w);                     \
    *reinterpret_cast<float4*>(&(H)[off]) = _h;                              \
    *reinterpret_cast<float4*>(&(L)[off]) = _l;                              \
} while (0)

#define STORE_TILES() do {                                                   \
    SPLIT4(ra0, AsH, AsL, ar0 * ASTR + ak0);                                 \
    SPLIT4(ra1, AsH, AsL, ar1 * ASTR + ak1);                                 \
    SPLIT4(rb0, BsH, BsL, bk0 * BSTR + bn0q);                                \
    SPLIT4(rb1, BsH, BsL, bk1 * BSTR + bn1q);                                \
} while (0)

    STORE_TILES();
    __syncthreads();

    const int NITER = DD / 16;
    for (int it = 0; it < NITER; it++) {
        if (it + 1 < NITER) {
            const int k0 = (it + 1) * 16;
            ra0 = *reinterpret_cast<const float4*>(&A[(long)(m0 + ar0) * DD + k0 + ak0]);
            ra1 = *reinterpret_cast<const float4*>(&A[(long)(m0 + ar1) * DD + k0 + ak1]);
            rb0 = *reinterpret_cast<const float4*>(&W[(long)(k0 + bk0) * DD + n0 + bn0q]);
            rb1 = *reinterpret_cast<const float4*>(&W[(long)(k0 + bk1) * DD + n0 + bn1q]);
        }

#pragma unroll
        for (int ks = 0; ks < 16; ks += 8) {
            uint32_t afH[4][4], afL[4][4], bfH[4][2], bfL[4][2];
            const int kk = ks + (lane & 3);
            const int rr = (lane >> 2);
#pragma unroll
            for (int mi = 0; mi < 4; mi++) {
                const int r = wm * 64 + mi * 16 + rr;
                afH[mi][0] = __float_as_uint(AsH[r * ASTR + kk]);
                afH[mi][1] = __float_as_uint(AsH[(r + 8) * ASTR + kk]);
                afH[mi][2] = __float_as_uint(AsH[r * ASTR + kk + 4]);
                afH[mi][3] = __float_as_uint(AsH[(r + 8) * ASTR + kk + 4]);
                afL[mi][0] = __float_as_uint(AsL[r * ASTR + kk]);
                afL[mi][1] = __float_as_uint(AsL[(r + 8) * ASTR + kk]);
                afL[mi][2] = __float_as_uint(AsL[r * ASTR + kk + 4]);
                afL[mi][3] = __float_as_uint(AsL[(r + 8) * ASTR + kk + 4]);
            }
#pragma unroll
            for (int ni = 0; ni < 4; ni++) {
                const int c = wn * 32 + ni * 8 + rr;
                bfH[ni][0] = __float_as_uint(BsH[kk * BSTR + c]);
                bfH[ni][1] = __float_as_uint(BsH[(kk + 4) * BSTR + c]);
                bfL[ni][0] = __float_as_uint(BsL[kk * BSTR + c]);
                bfL[ni][1] = __float_as_uint(BsL[(kk + 4) * BSTR + c]);
            }
#pragma unroll
            for (int mi = 0; mi < 4; mi++)
#pragma unroll
                for (int ni = 0; ni < 4; ni++) {
                    mma_tf32(acc[mi][ni], afH[mi], bfL[ni]);
                    mma_tf32(acc[mi][ni], afL[mi], bfH[ni]);
                    mma_tf32(acc[mi][ni], afH[mi], bfH[ni]);
                }
        }
        __syncthreads();
        if (it + 1 < NITER) {
            STORE_TILES();
            __syncthreads();
        }
    }

    const int rr = lane >> 2;
    const int cc = (lane & 3) * 2;
#pragma unroll
    for (int mi = 0; mi < 4; mi++) {
#pragma unroll
        for (int ni = 0; ni < 4; ni++) {
            const int col = wn * 32 + ni * 8 + cc;
            const int row = m0 + wm * 64 + mi * 16 + rr;
            float2 o0, o1;
            o0.x = acc[mi][ni][0] + sbias[col];
            o0.y = acc[mi][ni][1] + sbias[col + 1];
            o1.x = acc[mi][ni][2] + sbias[col];
            o1.y = acc[mi][ni][3] + sbias[col + 1];
            *reinterpret_cast<float2*>(&C[(long)row * DD + n0 + col]) = o0;
            *reinterpret_cast<float2*>(&C[(long)(row + 8) * DD + n0 + col]) = o1;
        }
    }
}

// ---------------------------------------------------------------------------
// Pre-pass: split Q/K into packed bf16 hi/lo pairs; V transposed-packed.
// ---------------------------------------------------------------------------
__global__ void __launch_bounds__(256)
split_qk_kernel()
{
    const int idx = blockIdx.x * 256 + threadIdx.x;   // < MM*DP
    float2 q2 = *reinterpret_cast<const float2*>(&g_q[(long)idx * 2]);
    split2(q2.x, q2.y, g_qh[idx], g_ql[idx]);
    float2 k2 = *reinterpret_cast<const float2*>(&g_k[(long)idx * 2]);
    split2(k2.x, k2.y, g_kh[idx], g_kl[idx]);
}

__global__ void __launch_bounds__(256)
split_vt_kernel()
{
    const int idx = blockIdx.x * 256 + threadIdx.x;   // < BB*HH*(SS/2)*DH
    const int d  = idx & 63;
    const int kp = (idx >> 6) & 1023;
    const int bh = idx >> 16;
    const int b  = bh / HH;
    const int h  = bh % HH;
    const long base = (long)(b * SS + 2 * kp) * DD + h * DH + d;
    uint32_t hi, lo;
    split2(g_v[base], g_v[base + DD], hi, lo);
    g_vth[idx] = hi;
    g_vtl[idx] = lo;
}

// ---------------------------------------------------------------------------
// Flash attention: bf16x3 mma.sync, register softmax, pre-split inputs.
// CTA = 128 queries x one (b,h); 8 warps, each owns m16 x full n64.
// ---------------------------------------------------------------------------
#define KSTR 33

__global__ void __launch_bounds__(256)
attn_kernel()
{
    __shared__ uint32_t sKh[64 * KSTR];
    __shared__ uint32_t sKl[64 * KSTR];
    __shared__ uint32_t sVh[64 * KSTR];
    __shared__ uint32_t sVl[64 * KSTR];

    const int tid  = threadIdx.x;
    const int warp = tid >> 5;
    const int lane = tid & 31;
    const int g    = lane >> 2;
    const int tg   = lane & 3;
    const int wm   = warp * 16;
    const int bh   = blockIdx.y;
    const int b    = bh / HH;
    const int h    = bh % HH;
    const int q0   = blockIdx.x * 128;

    // Q fragments to registers (once)
    uint32_t qH[4][4], qL[4][4];
    {
        const uint32_t* qh = &g_qh[(long)(b * SS + q0 + wm) * DP + h * 32];
        const uint32_t* ql = &g_ql[(long)(b * SS + q0 + wm) * DP + h * 32];
#pragma unroll
        for (int ks = 0; ks < 4; ks++) {
            const int c = ks * 8 + tg;
            qH[ks][0] = qh[g * DP + c];
            qH[ks][1] = qh[(g + 8) * DP + c];
            qH[ks][2] = qh[g * DP + c + 4];
            qH[ks][3] = qh[(g + 8) * DP + c + 4];
            qL[ks][0] = ql[g * DP + c];
            qL[ks][1] = ql[(g + 8) * DP + c];
            qL[ks][2] = ql[g * DP + c + 4];
            qL[ks][3] = ql[(g + 8) * DP + c + 4];
        }
    }

    float m0 = -INFINITY, m1 = -INFINITY, l0 = 0.0f, l1 = 0.0f;
    float o[8][4];
#pragma unroll
    for (int nt = 0; nt < 8; nt++)
#pragma unroll
        for (int q = 0; q < 4; q++) o[nt][q] = 0.0f;

    for (int kt = 0; kt < SS / 64; kt++) {
        const int k0 = kt * 64;
        // stage K tile (rows = key, cols = d-pairs)
        {
            const uint32_t* kh = &g_kh[(long)(b * SS + k0) * DP + h * 32];
            const uint32_t* kl = &g_kl[(long)(b * SS + k0) * DP + h * 32];
            for (int idx = tid; idx < 64 * 32; idx += 256) {
                const int r = idx >> 5, c = idx & 31;
                sKh[r * KSTR + c] = kh[(long)r * DP + c];
                sKl[r * KSTR + c] = kl[(long)r * DP + c];
            }
            // V tile (rows = d, cols = key-pairs), already transposed in gmem
            const uint32_t* vh = &g_vth[((long)(b * HH + h) * (SS / 2) + k0 / 2) * DH];
            const uint32_t* vl = &g_vtl[((long)(b * HH + h) * (SS / 2) + k0 / 2) * DH];
            for (int idx = tid; idx < 64 * 32; idx += 256) {
                const int d = idx & 63, kp = idx >> 6;
                sVh[d * KSTR + kp] = vh[kp * 64 + d];
                sVl[d * KSTR + kp] = vl[kp * 64 + d];
            }
        }
        __syncthreads();

        // S = Q @ K^T (bf16x3), fragments in registers
        float s[8][4];
#pragma unroll
        for (int nt = 0; nt < 8; nt++)
#pragma unroll
            for (int q = 0; q < 4; q++) s[nt][q] = 0.0f;
#pragma unroll
        for (int ks = 0; ks < 4; ks++) {
            const int co = ks * 8 + tg;
#pragma unroll
            for (int nt = 0; nt < 8; nt++) {
                const int n = nt * 8 + g;
                uint32_t bH[2] = { sKh[n * KSTR + co], sKh[n * KSTR + co + 4] };
                uint32_t bL[2] = { sKl[n * KSTR + co], sKl[n * KSTR + co + 4] };
                mma_bf16(s[nt], qH[ks], bL);
                mma_bf16(s[nt], qL[ks], bH);
                mma_bf16(s[nt], qH[ks], bH);
            }
        }

        // register softmax: rows g (s[][0..1]) and g+8 (s[][2..3])
        {
            float mx0 = -INFINITY, mx1 = -INFINITY;
#pragma unroll
            for (int nt = 0; nt < 8; nt++) {
                mx0 = fmaxf(mx0, fmaxf(s[nt][0], s[nt][1]));
                mx1 = fmaxf(mx1, fmaxf(s[nt][2], s[nt][3]));
            }
            mx0 = fmaxf(mx0, __shfl_xor_sync(0xffffffffu, mx0, 1));
            mx0 = fmaxf(mx0, __shfl_xor_sync(0xffffffffu, mx0, 2));
            mx1 = fmaxf(mx1, __shfl_xor_sync(0xffffffffu, mx1, 1));
            mx1 = fmaxf(mx1, __shfl_xor_sync(0xffffffffu, mx1, 2));
            const float m0n = fmaxf(m0, mx0);
            const float m1n = fmaxf(m1, mx1);
            const float fr0 = __expf(m0 - m0n);
            const float fr1 = __expf(m1 - m1n);
            m0 = m0n; m1 = m1n;
            float sum0 = 0.0f, sum1 = 0.0f;
#pragma unroll
            for (int nt = 0; nt < 8; nt++) {
                s[nt][0] = __expf(s[nt][0] - m0n);
                s[nt][1] = __expf(s[nt][1] - m0n);
                s[nt][2] = __expf(s[nt][2] - m1n);
                s[nt][3] = __expf(s[nt][3] - m1n);
                sum0 += s[nt][0] + s[nt][1];
                sum1 += s[nt][2] + s[nt][3];
            }
            sum0 += __shfl_xor_sync(0xffffffffu, sum0, 1);
            sum0 += __shfl_xor_sync(0xffffffffu, sum0, 2);
            sum1 += __shfl_xor_sync(0xffffffffu, sum1, 1);
            sum1 += __shfl_xor_sync(0xffffffffu, sum1, 2);
            l0 = l0 * fr0 + sum0;
            l1 = l1 * fr1 + sum1;
#pragma unroll
            for (int nt = 0; nt < 8; nt++) {
                o[nt][0] *= fr0; o[nt][1] *= fr0;
                o[nt][2] *= fr1; o[nt][3] *= fr1;
            }
        }

        // O += P @ V (bf16x3); P C-fragments map directly to A-fragments
#pragma unroll
        for (int ks2 = 0; ks2 < 4; ks2++) {
            const int nt0 = 2 * ks2, nt1 = 2 * ks2 + 1;
            uint32_t aH[4], aL[4];
            split2(s[nt0][0], s[nt0][1], aH[0], aL[0]);
            split2(s[nt0][2], s[nt0][3], aH[1], aL[1]);
            split2(s[nt1][0], s[nt1][1], aH[2], aL[2]);
            split2(s[nt1][2], s[nt1][3], aH[3], aL[3]);
            const int co = ks2 * 8 + tg;
#pragma unroll
            for (int nt = 0; nt < 8; nt++) {
                const int d = nt * 8 + g;
                uint32_t bH[2] = { sVh[d * KSTR + co], sVh[d * KSTR + co + 4] };
                uint32_t bL[2] = { sVl[d * KSTR + co], sVl[d * KSTR + co + 4] };
                mma_bf16(o[nt], aH, bL);
                mma_bf16(o[nt], aL, bH);
                mma_bf16(o[nt], aH, bH);
            }
        }
        __syncthreads();
    }

    // normalize and write ctx
    {
        const float i0 = 1.0f / l0;
        const float i1 = 1.0f / l1;
        const long r0g = (long)(b * SS + q0 + wm + g) * DD + h * DH;
        const long r1g = (long)(b * SS + q0 + wm + g + 8) * DD + h * DH;
#pragma unroll
        for (int nt = 0; nt < 8; nt++) {
            const int dcol = nt * 8 + 2 * tg;
            float2 w0, w1;
            w0.x = o[nt][0] * i0; w0.y = o[nt][1] * i0;
            w1.x = o[nt][2] * i1; w1.y = o[nt][3] * i1;
            *reinterpret_cast<float2*>(&g_ctx[r0g + dcol]) = w0;
            *reinterpret_cast<float2*>(&g_ctx[r1g + dcol]) = w1;
        }
    }
}

// ---------------------------------------------------------------------------
// Launch
// ---------------------------------------------------------------------------
extern "C" void kernel_launch(void* const* d_in, const int* in_sizes, int n_in,
                              void* d_out, int out_size)
{
    const float* x  = (const float*)d_in[0];
    const float* Wq = (const float*)d_in[1];
    const float* bq = (const float*)d_in[2];
    const float* Wk = (const float*)d_in[3];
    const float* bk = (const float*)d_in[4];
    const float* Wv = (const float*)d_in[5];
    const float* bv = (const float*)d_in[6];
    const float* Wo = (const float*)d_in[7];
    const float* bo = (const float*)d_in[8];
    float* out = (float*)d_out;

    void *pq, *pk, *pv, *pctx;
    cudaGetSymbolAddress(&pq,   g_q);
    cudaGetSymbolAddress(&pk,   g_k);
    cudaGetSymbolAddress(&pv,   g_v);
    cudaGetSymbolAddress(&pctx, g_ctx);

    dim3 ggrid(DD / 128, MM / 128);   // (6, 32)

    gemm_tf32_kernel<<<ggrid, 256>>>(x, Wq, bq, (float*)pq);
    gemm_tf32_kernel<<<ggrid, 256>>>(x, Wk, bk, (float*)pk);
    gemm_tf32_kernel<<<ggrid, 256>>>(x, Wv, bv, (float*)pv);

    // pre-split into packed bf16 hi/lo
    split_qk_kernel<<<MM * DP / 256, 256>>>();
    split_vt_kernel<<<MM * DP / 256, 256>>>();

    dim3 agrid(SS / 128, BB * HH);    // (16, 24)
    attn_kernel<<<agrid, 256>>>();

    gemm_tf32_kernel<<<ggrid, 256>>>((const float*)pctx, Wo, bo, out);
}

// round 10
// speedup vs baseline: 1.5737x; 1.2339x over previous
#include <cuda_runtime.h>
#include <cuda_bf16.h>
#include <math.h>
#include <stdint.h>

#define BB 2
#define SS 2048
#define DD 768
#define HH 12
#define DH 64
#define MM (BB*SS)
#define DP (DD/2)     // 384 u32 pairs per row

// scratch (no allocations allowed — __device__ globals are the sanctioned path)
__device__ float g_q[MM*DD];
__device__ float g_k[MM*DD];
__device__ float g_v[MM*DD];
__device__ float g_ctx[MM*DD];
// packed bf16 hi/lo splits (pre-pass output)
__device__ uint32_t g_qh[MM*DP];
__device__ uint32_t g_ql[MM*DP];
__device__ uint32_t g_kh[MM*DP];
__device__ uint32_t g_kl[MM*DP];
__device__ uint32_t g_vth[MM*DP];   // V transposed: [(b*HH+h)*1024 + kp][d]
__device__ uint32_t g_vtl[MM*DP];

__device__ __forceinline__ void mma_bf16(float* d,
                                         const uint32_t* a,
                                         const uint32_t* b) {
    asm volatile(
        "mma.sync.aligned.m16n8k16.row.col.f32.bf16.bf16.f32 "
        "{%0,%1,%2,%3}, {%4,%5,%6,%7}, {%8,%9}, {%0,%1,%2,%3};"
        : "+f"(d[0]), "+f"(d[1]), "+f"(d[2]), "+f"(d[3])
        : "r"(a[0]), "r"(a[1]), "r"(a[2]), "r"(a[3]),
          "r"(b[0]), "r"(b[1]));
}

// split (a,b) into packed bf16 hi-pair and lo-pair (low half = first element)
__device__ __forceinline__ void split2(float a, float b,
                                       uint32_t& hi, uint32_t& lo) {
    __nv_bfloat16 ah = __float2bfloat16(a);
    __nv_bfloat16 bh = __float2bfloat16(b);
    __nv_bfloat16 al = __float2bfloat16(a - __bfloat162float(ah));
    __nv_bfloat16 bl = __float2bfloat16(b - __bfloat162float(bh));
    hi = (uint32_t)__bfloat16_as_ushort(ah) |
         ((uint32_t)__bfloat16_as_ushort(bh) << 16);
    lo = (uint32_t)__bfloat16_as_ushort(al) |
         ((uint32_t)__bfloat16_as_ushort(bl) << 16);
}

// ---------------------------------------------------------------------------
// bf16x3 mma.sync GEMM: C[M,768] = A[M,768] @ W[768,768] + bias
// Packed-u32 bf16 hi/lo smem tiles; m16n8k16; BM=BN=128, BK=16, 256 threads,
// 8 warps (2x4), warp tile 64x32.
// ---------------------------------------------------------------------------
#define AST 9      // A smem u32 stride (8 kp + 1 pad)
#define BST 136    // B smem u32 stride (128 + 8 pad; 8*tg+g conflict-free)

__global__ void __launch_bounds__(256)
gemm_bf16_kernel(const float* __restrict__ A, const float* __restrict__ W,
                 const float* __restrict__ bias, float* __restrict__ C)
{
    __shared__ uint32_t AsH[128 * AST];
    __shared__ uint32_t AsL[128 * AST];
    __shared__ uint32_t BsH[8 * BST];
    __shared__ uint32_t BsL[8 * BST];
    __shared__ float sbias[128];

    const int tid  = threadIdx.x;
    const int warp = tid >> 5;
    const int lane = tid & 31;
    const int g    = lane >> 2;
    const int tg   = lane & 3;
    const int wm   = warp >> 2;          // 0..1 -> M offset wm*64
    const int wn   = warp & 3;           // 0..3 -> N offset wn*32
    const int m0   = blockIdx.y * 128;
    const int n0   = blockIdx.x * 128;

    if (tid < 128) sbias[tid] = bias[n0 + tid];

    // A loader: 2 float4 per thread (rows 0..127, 4 float4 per 16-wide row)
    const int ar0 = tid >> 2;
    const int aq0 = tid & 3;             // float4 idx -> kp offset aq*2
    const int ar1 = (tid + 256) >> 2;
    const int aq1 = (tid + 256) & 3;
    // B loader: one (kp, 4n) group per thread; loads rows 2kp and 2kp+1
    const int bkp = tid >> 5;            // 0..7
    const int bnq = (tid & 31) << 2;     // 0..124

    float acc[4][4][4];
#pragma unroll
    for (int i = 0; i < 4; i++)
#pragma unroll
        for (int j = 0; j < 4; j++)
#pragma unroll
            for (int q = 0; q < 4; q++) acc[i][j][q] = 0.0f;

    float4 ra0, ra1, rb0, rb1;

    ra0 = *reinterpret_cast<const float4*>(&A[(long)(m0 + ar0) * DD + aq0 * 4]);
    ra1 = *reinterpret_cast<const float4*>(&A[(long)(m0 + ar1) * DD + aq1 * 4]);
    rb0 = *reinterpret_cast<const float4*>(&W[(long)(2 * bkp) * DD + n0 + bnq]);
    rb1 = *reinterpret_cast<const float4*>(&W[(long)(2 * bkp + 1) * DD + n0 + bnq]);

#define STORE_TILES() do {                                                   \
    split2(ra0.x, ra0.y, AsH[ar0 * AST + aq0 * 2],     AsL[ar0 * AST + aq0 * 2]); \
    split2(ra0.z, ra0.w, AsH[ar0 * AST + aq0 * 2 + 1], AsL[ar0 * AST + aq0 * 2 + 1]); \
    split2(ra1.x, ra1.y, AsH[ar1 * AST + aq1 * 2],     AsL[ar1 * AST + aq1 * 2]); \
    split2(ra1.z, ra1.w, AsH[ar1 * AST + aq1 * 2 + 1], AsL[ar1 * AST + aq1 * 2 + 1]); \
    split2(rb0.x, rb1.x, BsH[bkp * BST + bnq],     BsL[bkp * BST + bnq]);     \
    split2(rb0.y, rb1.y, BsH[bkp * BST + bnq + 1], BsL[bkp * BST + bnq + 1]); \
    split2(rb0.z, rb1.z, BsH[bkp * BST + bnq + 2], BsL[bkp * BST + bnq + 2]); \
    split2(rb0.w, rb1.w, BsH[bkp * BST + bnq + 3], BsL[bkp * BST + bnq + 3]); \
} while (0)

    STORE_TILES();
    __syncthreads();

    const int NITER = DD / 16;   // 48
    for (int it = 0; it < NITER; it++) {
        if (it + 1 < NITER) {
            const int k0 = (it + 1) * 16;
            ra0 = *reinterpret_cast<const float4*>(&A[(long)(m0 + ar0) * DD + k0 + aq0 * 4]);
            ra1 = *reinterpret_cast<const float4*>(&A[(long)(m0 + ar1) * DD + k0 + aq1 * 4]);
            rb0 = *reinterpret_cast<const float4*>(&W[(long)(k0 + 2 * bkp) * DD + n0 + bnq]);
            rb1 = *reinterpret_cast<const float4*>(&W[(long)(k0 + 2 * bkp + 1) * DD + n0 + bnq]);
        }

        // fragments (one k16 step per iter)
        uint32_t afH[4][4], afL[4][4], bfH[4][2], bfL[4][2];
#pragma unroll
        for (int mi = 0; mi < 4; mi++) {
            const int r = wm * 64 + mi * 16 + g;
            afH[mi][0] = AsH[r * AST + tg];
            afH[mi][1] = AsH[(r + 8) * AST + tg];
            afH[mi][2] = AsH[r * AST + tg + 4];
            afH[mi][3] = AsH[(r + 8) * AST + tg + 4];
            afL[mi][0] = AsL[r * AST + tg];
            afL[mi][1] = AsL[(r + 8) * AST + tg];
            afL[mi][2] = AsL[r * AST + tg + 4];
            afL[mi][3] = AsL[(r + 8) * AST + tg + 4];
        }
#pragma unroll
        for (int ni = 0; ni < 4; ni++) {
            const int c = wn * 32 + ni * 8 + g;
            bfH[ni][0] = BsH[tg * BST + c];
            bfH[ni][1] = BsH[(tg + 4) * BST + c];
            bfL[ni][0] = BsL[tg * BST + c];
            bfL[ni][1] = BsL[(tg + 4) * BST + c];
        }
#pragma unroll
        for (int mi = 0; mi < 4; mi++)
#pragma unroll
            for (int ni = 0; ni < 4; ni++) {
                mma_bf16(acc[mi][ni], afH[mi], bfL[ni]);
                mma_bf16(acc[mi][ni], afL[mi], bfH[ni]);
                mma_bf16(acc[mi][ni], afH[mi], bfH[ni]);
            }
        __syncthreads();
        if (it + 1 < NITER) {
            STORE_TILES();
            __syncthreads();
        }
    }

    // epilogue: bias + store
    const int rr = lane >> 2;
    const int cc = (lane & 3) * 2;
#pragma unroll
    for (int mi = 0; mi < 4; mi++) {
#pragma unroll
        for (int ni = 0; ni < 4; ni++) {
            const int col = wn * 32 + ni * 8 + cc;
            const int row = m0 + wm * 64 + mi * 16 + rr;
            float2 o0, o1;
            o0.x = acc[mi][ni][0] + sbias[col];
            o0.y = acc[mi][ni][1] + sbias[col + 1];
            o1.x = acc[mi][ni][2] + sbias[col];
            o1.y = acc[mi][ni][3] + sbias[col + 1];
            *reinterpret_cast<float2*>(&C[(long)row * DD + n0 + col]) = o0;
            *reinterpret_cast<float2*>(&C[(long)(row + 8) * DD + n0 + col]) = o1;
        }
    }
}

// ---------------------------------------------------------------------------
// Pre-pass: split Q/K into packed bf16 hi/lo pairs; V transposed-packed.
// ---------------------------------------------------------------------------
__global__ void __launch_bounds__(256)
split_qk_kernel()
{
    const int idx = blockIdx.x * 256 + threadIdx.x;   // < MM*DP
    float2 q2 = *reinterpret_cast<const float2*>(&g_q[(long)idx * 2]);
    split2(q2.x, q2.y, g_qh[idx], g_ql[idx]);
    float2 k2 = *reinterpret_cast<const float2*>(&g_k[(long)idx * 2]);
    split2(k2.x, k2.y, g_kh[idx], g_kl[idx]);
}

__global__ void __launch_bounds__(256)
split_vt_kernel()
{
    const int idx = blockIdx.x * 256 + threadIdx.x;   // < BB*HH*(SS/2)*DH
    const int d  = idx & 63;
    const int kp = (idx >> 6) & 1023;
    const int bh = idx >> 16;
    const int b  = bh / HH;
    const int h  = bh % HH;
    const long base = (long)(b * SS + 2 * kp) * DD + h * DH + d;
    uint32_t hi, lo;
    split2(g_v[base], g_v[base + DD], hi, lo);
    g_vth[idx] = hi;
    g_vtl[idx] = lo;
}

// ---------------------------------------------------------------------------
// Flash attention: bf16x3 mma.sync, register softmax, pre-split inputs.
// CTA = 128 queries x one (b,h); 8 warps, each owns m16 x full n64.
// ---------------------------------------------------------------------------
#define KSTR 33

__global__ void __launch_bounds__(256)
attn_kernel()
{
    __shared__ uint32_t sKh[64 * KSTR];
    __shared__ uint32_t sKl[64 * KSTR];
    __shared__ uint32_t sVh[64 * KSTR];
    __shared__ uint32_t sVl[64 * KSTR];

    const int tid  = threadIdx.x;
    const int warp = tid >> 5;
    const int lane = tid & 31;
    const int g    = lane >> 2;
    const int tg   = lane & 3;
    const int wm   = warp * 16;
    const int bh   = blockIdx.y;
    const int b    = bh / HH;
    const int h    = bh % HH;
    const int q0   = blockIdx.x * 128;

    // Q fragments to registers (once)
    uint32_t qH[4][4], qL[4][4];
    {
        const uint32_t* qh = &g_qh[(long)(b * SS + q0 + wm) * DP + h * 32];
        const uint32_t* ql = &g_ql[(long)(b * SS + q0 + wm) * DP + h * 32];
#pragma unroll
        for (int ks = 0; ks < 4; ks++) {
            const int c = ks * 8 + tg;
            qH[ks][0] = qh[g * DP + c];
            qH[ks][1] = qh[(g + 8) * DP + c];
            qH[ks][2] = qh[g * DP + c + 4];
            qH[ks][3] = qh[(g + 8) * DP + c + 4];
            qL[ks][0] = ql[g * DP + c];
            qL[ks][1] = ql[(g + 8) * DP + c];
            qL[ks][2] = ql[g * DP + c + 4];
            qL[ks][3] = ql[(g + 8) * DP + c + 4];
        }
    }

    float m0 = -INFINITY, m1 = -INFINITY, l0 = 0.0f, l1 = 0.0f;
    float o[8][4];
#pragma unroll
    for (int nt = 0; nt < 8; nt++)
#pragma unroll
        for (int q = 0; q < 4; q++) o[nt][q] = 0.0f;

    for (int kt = 0; kt < SS / 64; kt++) {
        const int k0 = kt * 64;
        // stage K tile (rows = key, cols = d-pairs)
        {
            const uint32_t* kh = &g_kh[(long)(b * SS + k0) * DP + h * 32];
            const uint32_t* kl = &g_kl[(long)(b * SS + k0) * DP + h * 32];
            for (int idx = tid; idx < 64 * 32; idx += 256) {
                const int r = idx >> 5, c = idx & 31;
                sKh[r * KSTR + c] = kh[(long)r * DP + c];
                sKl[r * KSTR + c] = kl[(long)r * DP + c];
            }
            // V tile (rows = d, cols = key-pairs), already transposed in gmem
            const uint32_t* vh = &g_vth[((long)(b * HH + h) * (SS / 2) + k0 / 2) * DH];
            const uint32_t* vl = &g_vtl[((long)(b * HH + h) * (SS / 2) + k0 / 2) * DH];
            for (int idx = tid; idx < 64 * 32; idx += 256) {
                const int d = idx & 63, kp = idx >> 6;
                sVh[d * KSTR + kp] = vh[kp * 64 + d];
                sVl[d * KSTR + kp] = vl[kp * 64 + d];
            }
        }
        __syncthreads();

        // S = Q @ K^T (bf16x3), fragments in registers
        float s[8][4];
#pragma unroll
        for (int nt = 0; nt < 8; nt++)
#pragma unroll
            for (int q = 0; q < 4; q++) s[nt][q] = 0.0f;
#pragma unroll
        for (int ks = 0; ks < 4; ks++) {
            const int co = ks * 8 + tg;
#pragma unroll
            for (int nt = 0; nt < 8; nt++) {
                const int n = nt * 8 + g;
                uint32_t bH[2] = { sKh[n * KSTR + co], sKh[n * KSTR + co + 4] };
                uint32_t bL[2] = { sKl[n * KSTR + co], sKl[n * KSTR + co + 4] };
                mma_bf16(s[nt], qH[ks], bL);
                mma_bf16(s[nt], qL[ks], bH);
                mma_bf16(s[nt], qH[ks], bH);
            }
        }

        // register softmax: rows g (s[][0..1]) and g+8 (s[][2..3])
        {
            float mx0 = -INFINITY, mx1 = -INFINITY;
#pragma unroll
            for (int nt = 0; nt < 8; nt++) {
                mx0 = fmaxf(mx0, fmaxf(s[nt][0], s[nt][1]));
                mx1 = fmaxf(mx1, fmaxf(s[nt][2], s[nt][3]));
            }
            mx0 = fmaxf(mx0, __shfl_xor_sync(0xffffffffu, mx0, 1));
            mx0 = fmaxf(mx0, __shfl_xor_sync(0xffffffffu, mx0, 2));
            mx1 = fmaxf(mx1, __shfl_xor_sync(0xffffffffu, mx1, 1));
            mx1 = fmaxf(mx1, __shfl_xor_sync(0xffffffffu, mx1, 2));
            const float m0n = fmaxf(m0, mx0);
            const float m1n = fmaxf(m1, mx1);
            const float fr0 = __expf(m0 - m0n);
            const float fr1 = __expf(m1 - m1n);
            m0 = m0n; m1 = m1n;
            float sum0 = 0.0f, sum1 = 0.0f;
#pragma unroll
            for (int nt = 0; nt < 8; nt++) {
                s[nt][0] = __expf(s[nt][0] - m0n);
                s[nt][1] = __expf(s[nt][1] - m0n);
                s[nt][2] = __expf(s[nt][2] - m1n);
                s[nt][3] = __expf(s[nt][3] - m1n);
                sum0 += s[nt][0] + s[nt][1];
                sum1 += s[nt][2] + s[nt][3];
            }
            sum0 += __shfl_xor_sync(0xffffffffu, sum0, 1);
            sum0 += __shfl_xor_sync(0xffffffffu, sum0, 2);
            sum1 += __shfl_xor_sync(0xffffffffu, sum1, 1);
            sum1 += __shfl_xor_sync(0xffffffffu, sum1, 2);
            l0 = l0 * fr0 + sum0;
            l1 = l1 * fr1 + sum1;
#pragma unroll
            for (int nt = 0; nt < 8; nt++) {
                o[nt][0] *= fr0; o[nt][1] *= fr0;
                o[nt][2] *= fr1; o[nt][3] *= fr1;
            }
        }

        // O += P @ V (bf16x3); P C-fragments map directly to A-fragments
#pragma unroll
        for (int ks2 = 0; ks2 < 4; ks2++) {
            const int nt0 = 2 * ks2, nt1 = 2 * ks2 + 1;
            uint32_t aH[4], aL[4];
            split2(s[nt0][0], s[nt0][1], aH[0], aL[0]);
            split2(s[nt0][2], s[nt0][3], aH[1], aL[1]);
            split2(s[nt1][0], s[nt1][1], aH[2], aL[2]);
            split2(s[nt1][2], s[nt1][3], aH[3], aL[3]);
            const int co = ks2 * 8 + tg;
#pragma unroll
            for (int nt = 0; nt < 8; nt++) {
                const int d = nt * 8 + g;
                uint32_t bH[2] = { sVh[d * KSTR + co], sVh[d * KSTR + co + 4] };
                uint32_t bL[2] = { sVl[d * KSTR + co], sVl[d * KSTR + co + 4] };
                mma_bf16(o[nt], aH, bL);
                mma_bf16(o[nt], aL, bH);
                mma_bf16(o[nt], aH, bH);
            }
        }
        __syncthreads();
    }

    // normalize and write ctx
    {
        const float i0 = 1.0f / l0;
        const float i1 = 1.0f / l1;
        const long r0g = (long)(b * SS + q0 + wm + g) * DD + h * DH;
        const long r1g = (long)(b * SS + q0 + wm + g + 8) * DD + h * DH;
#pragma unroll
        for (int nt = 0; nt < 8; nt++) {
            const int dcol = nt * 8 + 2 * tg;
            float2 w0, w1;
            w0.x = o[nt][0] * i0; w0.y = o[nt][1] * i0;
            w1.x = o[nt][2] * i1; w1.y = o[nt][3] * i1;
            *reinterpret_cast<float2*>(&g_ctx[r0g + dcol]) = w0;
            *reinterpret_cast<float2*>(&g_ctx[r1g + dcol]) = w1;
        }
    }
}

// ---------------------------------------------------------------------------
// Launch
// ---------------------------------------------------------------------------
extern "C" void kernel_launch(void* const* d_in, const int* in_sizes, int n_in,
                              void* d_out, int out_size)
{
    const float* x  = (const float*)d_in[0];
    const float* Wq = (const float*)d_in[1];
    const float* bq = (const float*)d_in[2];
    const float* Wk = (const float*)d_in[3];
    const float* bk = (const float*)d_in[4];
    const float* Wv = (const float*)d_in[5];
    const float* bv = (const float*)d_in[6];
    const float* Wo = (const float*)d_in[7];
    const float* bo = (const float*)d_in[8];
    float* out = (float*)d_out;

    void *pq, *pk, *pv, *pctx;
    cudaGetSymbolAddress(&pq,   g_q);
    cudaGetSymbolAddress(&pk,   g_k);
    cudaGetSymbolAddress(&pv,   g_v);
    cudaGetSymbolAddress(&pctx, g_ctx);

    dim3 ggrid(DD / 128, MM / 128);   // (6, 32)

    gemm_bf16_kernel<<<ggrid, 256>>>(x, Wq, bq, (float*)pq);
    gemm_bf16_kernel<<<ggrid, 256>>>(x, Wk, bk, (float*)pk);
    gemm_bf16_kernel<<<ggrid, 256>>>(x, Wv, bv, (float*)pv);

    // pre-split into packed bf16 hi/lo
    split_qk_kernel<<<MM * DP / 256, 256>>>();
    split_vt_kernel<<<MM * DP / 256, 256>>>();

    dim3 agrid(SS / 128, BB * HH);    // (16, 24)
    attn_kernel<<<agrid, 256>>>();

    gemm_bf16_kernel<<<ggrid, 256>>>((const float*)pctx, Wo, bo, out);
}

// round 13
// speedup vs baseline: 2.8351x; 1.8015x over previous
#include <cuda_runtime.h>
#include <cuda_bf16.h>
#include <math.h>
#include <stdint.h>

#define BB 2
#define SS 2048
#define DD 768
#define HH 12
#define DH 64
#define MM (BB*SS)
#define DP (DD/2)     // 384 u32 pairs per row

// scratch (no allocations allowed — __device__ globals are the sanctioned path)
__device__ float g_v[MM*DD];
__device__ float g_ctx[MM*DD];
// packed bf16 hi/lo splits
__device__ uint32_t g_qh[MM*DP];
__device__ uint32_t g_ql[MM*DP];
__device__ uint32_t g_kh[MM*DP];
__device__ uint32_t g_kl[MM*DP];
__device__ uint32_t g_vth[MM*DP];   // V transposed: [(b*HH+h)*1024 + kp][d]
__device__ uint32_t g_vtl[MM*DP];

__device__ __forceinline__ void mma_bf16(float* d,
                                         const uint32_t* a,
                                         const uint32_t* b) {
    asm volatile(
        "mma.sync.aligned.m16n8k16.row.col.f32.bf16.bf16.f32 "
        "{%0,%1,%2,%3}, {%4,%5,%6,%7}, {%8,%9}, {%0,%1,%2,%3};"
        : "+f"(d[0]), "+f"(d[1]), "+f"(d[2]), "+f"(d[3])
        : "r"(a[0]), "r"(a[1]), "r"(a[2]), "r"(a[3]),
          "r"(b[0]), "r"(b[1]));
}

__device__ __forceinline__ void split2(float a, float b,
                                       uint32_t& hi, uint32_t& lo) {
    __nv_bfloat16 ah = __float2bfloat16(a);
    __nv_bfloat16 bh = __float2bfloat16(b);
    __nv_bfloat16 al = __float2bfloat16(a - __bfloat162float(ah));
    __nv_bfloat16 bl = __float2bfloat16(b - __bfloat162float(bh));
    hi = (uint32_t)__bfloat16_as_ushort(ah) |
         ((uint32_t)__bfloat16_as_ushort(bh) << 16);
    lo = (uint32_t)__bfloat16_as_ushort(al) |
         ((uint32_t)__bfloat16_as_ushort(bl) << 16);
}

__device__ __forceinline__ void cp16(uint32_t saddr, const void* gaddr) {
    asm volatile("cp.async.ca.shared.global [%0], [%1], 16;"
                 :: "r"(saddr), "l"(gaddr));
}
#define CP_COMMIT() asm volatile("cp.async.commit_group;" ::: "memory")
#define CP_WAIT1()  asm volatile("cp.async.wait_group 1;" ::: "memory")
#define CP_WAIT0()  asm volatile("cp.async.wait_group 0;" ::: "memory")

// ---------------------------------------------------------------------------
// bf16x3 mma.sync GEMM with selectable epilogue (float C, or packed hi/lo).
// grid.z selects weight/bias/output set (fused QKV in one launch).
// BM=BN=128, BK=16, 256 threads, warp tile 64x32.
// ---------------------------------------------------------------------------
struct GemmArgs {
    const float* W[3];
    const float* bias[3];
    float*    Cf[3];
    uint32_t* Ch[3];
    uint32_t* Cl[3];
};

#define AST 9      // A smem u32 stride
#define BST 136    // B smem u32 stride

__global__ void __launch_bounds__(256)
gemm_bf16_kernel(const float* __restrict__ A, GemmArgs args)
{
    __shared__ uint32_t AsH[128 * AST];
    __shared__ uint32_t AsL[128 * AST];
    __shared__ uint32_t BsH[8 * BST];
    __shared__ uint32_t BsL[8 * BST];
    __shared__ float sbias[128];

    const int z = blockIdx.z;
    const float* __restrict__ W    = args.W[z];
    const float* __restrict__ bias = args.bias[z];
    float*    Cf = args.Cf[z];
    uint32_t* Ch = args.Ch[z];
    uint32_t* Cl = args.Cl[z];

    const int tid  = threadIdx.x;
    const int warp = tid >> 5;
    const int lane = tid & 31;
    const int g    = lane >> 2;
    const int tg   = lane & 3;
    const int wm   = warp >> 2;
    const int wn   = warp & 3;
    const int m0   = blockIdx.y * 128;
    const int n0   = blockIdx.x * 128;

    if (tid < 128) sbias[tid] = bias[n0 + tid];

    const int ar0 = tid >> 2;
    const int aq0 = tid & 3;
    const int ar1 = (tid + 256) >> 2;
    const int aq1 = (tid + 256) & 3;
    const int bkp = tid >> 5;
    const int bnq = (tid & 31) << 2;

    float acc[4][4][4];
#pragma unroll
    for (int i = 0; i < 4; i++)
#pragma unroll
        for (int j = 0; j < 4; j++)
#pragma unroll
            for (int q = 0; q < 4; q++) acc[i][j][q] = 0.0f;

    float4 ra0, ra1, rb0, rb1;

    ra0 = *reinterpret_cast<const float4*>(&A[(long)(m0 + ar0) * DD + aq0 * 4]);
    ra1 = *reinterpret_cast<const float4*>(&A[(long)(m0 + ar1) * DD + aq1 * 4]);
    rb0 = *reinterpret_cast<const float4*>(&W[(long)(2 * bkp) * DD + n0 + bnq]);
    rb1 = *reinterpret_cast<const float4*>(&W[(long)(2 * bkp + 1) * DD + n0 + bnq]);

#define STORE_TILES() do {                                                   \
    split2(ra0.x, ra0.y, AsH[ar0 * AST + aq0 * 2],     AsL[ar0 * AST + aq0 * 2]); \
    split2(ra0.z, ra0.w, AsH[ar0 * AST + aq0 * 2 + 1], AsL[ar0 * AST + aq0 * 2 + 1]); \
    split2(ra1.x, ra1.y, AsH[ar1 * AST + aq1 * 2],     AsL[ar1 * AST + aq1 * 2]); \
    split2(ra1.z, ra1.w, AsH[ar1 * AST + aq1 * 2 + 1], AsL[ar1 * AST + aq1 * 2 + 1]); \
    split2(rb0.x, rb1.x, BsH[bkp * BST + bnq],     BsL[bkp * BST + bnq]);     \
    split2(rb0.y, rb1.y, BsH[bkp * BST + bnq + 1], BsL[bkp * BST + bnq + 1]); \
    split2(rb0.z, rb1.z, BsH[bkp * BST + bnq + 2], BsL[bkp * BST + bnq + 2]); \
    split2(rb0.w, rb1.w, BsH[bkp * BST + bnq + 3], BsL[bkp * BST + bnq + 3]); \
} while (0)

    STORE_TILES();
    __syncthreads();

    const int NITER = DD / 16;   // 48
    for (int it = 0; it < NITER; it++) {
        if (it + 1 < NITER) {
            const int k0 = (it + 1) * 16;
            ra0 = *reinterpret_cast<const float4*>(&A[(long)(m0 + ar0) * DD + k0 + aq0 * 4]);
            ra1 = *reinterpret_cast<const float4*>(&A[(long)(m0 + ar1) * DD + k0 + aq1 * 4]);
            rb0 = *reinterpret_cast<const float4*>(&W[(long)(k0 + 2 * bkp) * DD + n0 + bnq]);
            rb1 = *reinterpret_cast<const float4*>(&W[(long)(k0 + 2 * bkp + 1) * DD + n0 + bnq]);
        }

        uint32_t afH[4][4], afL[4][4], bfH[4][2], bfL[4][2];
#pragma unroll
        for (int mi = 0; mi < 4; mi++) {
            const int r = wm * 64 + mi * 16 + g;
            afH[mi][0] = AsH[r * AST + tg];
            afH[mi][1] = AsH[(r + 8) * AST + tg];
            afH[mi][2] = AsH[r * AST + tg + 4];
            afH[mi][3] = AsH[(r + 8) * AST + tg + 4];
            afL[mi][0] = AsL[r * AST + tg];
            afL[mi][1] = AsL[(r + 8) * AST + tg];
            afL[mi][2] = AsL[r * AST + tg + 4];
            afL[mi][3] = AsL[(r + 8) * AST + tg + 4];
        }
#pragma unroll
        for (int ni = 0; ni < 4; ni++) {
            const int c = wn * 32 + ni * 8 + g;
            bfH[ni][0] = BsH[tg * BST + c];
            bfH[ni][1] = BsH[(tg + 4) * BST + c];
            bfL[ni][0] = BsL[tg * BST + c];
            bfL[ni][1] = BsL[(tg + 4) * BST + c];
        }
#pragma unroll
        for (int mi = 0; mi < 4; mi++)
#pragma unroll
            for (int ni = 0; ni < 4; ni++) {
                mma_bf16(acc[mi][ni], afH[mi], bfL[ni]);
                mma_bf16(acc[mi][ni], afL[mi], bfH[ni]);
                mma_bf16(acc[mi][ni], afH[mi], bfH[ni]);
            }
        __syncthreads();
        if (it + 1 < NITER) {
            STORE_TILES();
            __syncthreads();
        }
    }

    // epilogue
    const int rr = lane >> 2;
    const int cc = (lane & 3) * 2;
    if (Ch) {
        // packed bf16 hi/lo output (Q/K path)
#pragma unroll
        for (int mi = 0; mi < 4; mi++) {
#pragma unroll
            for (int ni = 0; ni < 4; ni++) {
                const int col = wn * 32 + ni * 8 + cc;
                const int row = m0 + wm * 64 + mi * 16 + rr;
                const int pc  = (n0 + col) >> 1;
                const float v0 = acc[mi][ni][0] + sbias[col];
                const float v1 = acc[mi][ni][1] + sbias[col + 1];
                const float v2 = acc[mi][ni][2] + sbias[col];
                const float v3 = acc[mi][ni][3] + sbias[col + 1];
                uint32_t hi, lo;
                split2(v0, v1, hi, lo);
                Ch[(long)row * DP + pc] = hi;
                Cl[(long)row * DP + pc] = lo;
                split2(v2, v3, hi, lo);
                Ch[(long)(row + 8) * DP + pc] = hi;
                Cl[(long)(row + 8) * DP + pc] = lo;
            }
        }
    } else {
        // float output (V and O paths)
#pragma unroll
        for (int mi = 0; mi < 4; mi++) {
#pragma unroll
            for (int ni = 0; ni < 4; ni++) {
                const int col = wn * 32 + ni * 8 + cc;
                const int row = m0 + wm * 64 + mi * 16 + rr;
                float2 o0, o1;
                o0.x = acc[mi][ni][0] + sbias[col];
                o0.y = acc[mi][ni][1] + sbias[col + 1];
                o1.x = acc[mi][ni][2] + sbias[col];
                o1.y = acc[mi][ni][3] + sbias[col + 1];
                *reinterpret_cast<float2*>(&Cf[(long)row * DD + n0 + col]) = o0;
                *reinterpret_cast<float2*>(&Cf[(long)(row + 8) * DD + n0 + col]) = o1;
            }
        }
    }
}

// ---------------------------------------------------------------------------
// Pre-pass: V transposed-packed split.
// ---------------------------------------------------------------------------
__global__ void __launch_bounds__(256)
split_vt_kernel()
{
    const int idx = blockIdx.x * 256 + threadIdx.x;   // < BB*HH*(SS/2)*DH
    const int d  = idx & 63;
    const int kp = (idx >> 6) & 1023;
    const int bh = idx >> 16;
    const int b  = bh / HH;
    const int h  = bh % HH;
    const long base = (long)(b * SS + 2 * kp) * DD + h * DH + d;
    uint32_t hi, lo;
    split2(g_v[base], g_v[base + DD], hi, lo);
    g_vth[idx] = hi;
    g_vtl[idx] = lo;
}

// ---------------------------------------------------------------------------
// Flash attention: bf16x3 mma.sync, register softmax, cp.async double-buffer.
// CTA = 128 queries x one (b,h); 8 warps, each owns m16 x full n64.
// K tiles: [key(64)][dpair(32)] stride 36; V tiles: [kp(32)][d(64)] stride 72.
// ---------------------------------------------------------------------------
#define KTILE 2304                      // 64*36 == 32*72 u32 per array per stage
#define ATT_SMEM (8 * KTILE * 4)        // 73728 B
#define NT (SS/64)                      // 32

__global__ void __launch_bounds__(256)
attn_kernel()
{
    extern __shared__ uint32_t smatt[];
    uint32_t* sKh = smatt;
    uint32_t* sKl = smatt + 2 * KTILE;
    uint32_t* sVh = smatt + 4 * KTILE;
    uint32_t* sVl = smatt + 6 * KTILE;

    const uint32_t aKh = (uint32_t)__cvta_generic_to_shared(sKh);
    const uint32_t aKl = (uint32_t)__cvta_generic_to_shared(sKl);
    const uint32_t aVh = (uint32_t)__cvta_generic_to_shared(sVh);
    const uint32_t aVl = (uint32_t)__cvta_generic_to_shared(sVl);

    const int tid  = threadIdx.x;
    const int warp = tid >> 5;
    const int lane = tid & 31;
    const int g    = lane >> 2;
    const int tg   = lane & 3;
    const int wm   = warp * 16;
    const int bh   = blockIdx.y;
    const int b    = bh / HH;
    const int h    = bh % HH;
    const int q0   = blockIdx.x * 128;

    const uint32_t* khg = &g_kh[(long)(b * SS) * DP + h * 32];
    const uint32_t* klg = &g_kl[(long)(b * SS) * DP + h * 32];
    const uint32_t* vhg = &g_vth[(long)(b * HH + h) * (SS / 2) * 64];
    const uint32_t* vlg = &g_vtl[(long)(b * HH + h) * (SS / 2) * 64];

    // staging coords (2 chunks per array per thread)
    const int kr0 = tid >> 3,            kq0 = (tid & 7) * 4;
    const int kr1 = (tid + 256) >> 3,    kq1 = ((tid + 256) & 7) * 4;
    const int vr0 = tid >> 4,            vq0 = (tid & 15) * 4;
    const int vr1 = (tid + 256) >> 4,    vq1 = ((tid + 256) & 15) * 4;

#define ISSUE_STAGE(kt, st) do {                                             \
    const int _k0 = (kt) * 64;                                               \
    const uint32_t _so = (uint32_t)(st) * KTILE * 4;                         \
    cp16(aKh + _so + (kr0 * 36 + kq0) * 4, khg + (long)(_k0 + kr0) * DP + kq0); \
    cp16(aKh + _so + (kr1 * 36 + kq1) * 4, khg + (long)(_k0 + kr1) * DP + kq1); \
    cp16(aKl + _so + (kr0 * 36 + kq0) * 4, klg + (long)(_k0 + kr0) * DP + kq0); \
    cp16(aKl + _so + (kr1 * 36 + kq1) * 4, klg + (long)(_k0 + kr1) * DP + kq1); \
    cp16(aVh + _so + (vr0 * 72 + vq0) * 4, vhg + (long)(_k0 / 2 + vr0) * 64 + vq0); \
    cp16(aVh + _so + (vr1 * 72 + vq1) * 4, vhg + (long)(_k0 / 2 + vr1) * 64 + vq1); \
    cp16(aVl + _so + (vr0 * 72 + vq0) * 4, vlg + (long)(_k0 / 2 + vr0) * 64 + vq0); \
    cp16(aVl + _so + (vr1 * 72 + vq1) * 4, vlg + (long)(_k0 / 2 + vr1) * 64 + vq1); \
    CP_COMMIT();                                                             \
} while (0)

    // Q fragments to registers (once)
    uint32_t qH[4][4], qL[4][4];
    {
        const uint32_t* qh = &g_qh[(long)(b * SS + q0 + wm) * DP + h * 32];
        const uint32_t* ql = &g_ql[(long)(b * SS + q0 + wm) * DP + h * 32];
#pragma unroll
        for (int ks = 0; ks < 4; ks++) {
            const int c = ks * 8 + tg;
            qH[ks][0] = qh[g * DP + c];
            qH[ks][1] = qh[(g + 8) * DP + c];
            qH[ks][2] = qh[g * DP + c + 4];
            qH[ks][3] = qh[(g + 8) * DP + c + 4];
            qL[ks][0] = ql[g * DP + c];
            qL[ks][1] = ql[(g + 8) * DP + c];
            qL[ks][2] = ql[g * DP + c + 4];
            qL[ks][3] = ql[(g + 8) * DP + c + 4];
        }
    }

    float m0 = -INFINITY, m1 = -INFINITY, l0 = 0.0f, l1 = 0.0f;
    float o[8][4];
#pragma unroll
    for (int nt = 0; nt < 8; nt++)
#pragma unroll
        for (int q = 0; q < 4; q++) o[nt][q] = 0.0f;

    ISSUE_STAGE(0, 0);

    for (int kt = 0; kt < NT; kt++) {
        const int st = kt & 1;
        if (kt + 1 < NT) {
            ISSUE_STAGE(kt + 1, st ^ 1);
            CP_WAIT1();
        } else {
            CP_WAIT0();
        }
        __syncthreads();

        const uint32_t* kh = sKh + st * KTILE;
        const uint32_t* kl = sKl + st * KTILE;
        const uint32_t* vh = sVh + st * KTILE;
        const uint32_t* vl = sVl + st * KTILE;

        // S = Q @ K^T (bf16x3)
        float s[8][4];
#pragma unroll
        for (int nt = 0; nt < 8; nt++)
#pragma unroll
            for (int q = 0; q < 4; q++) s[nt][q] = 0.0f;
#pragma unroll
        for (int ks = 0; ks < 4; ks++) {
            const int co = ks * 8 + tg;
#pragma unroll
            for (int nt = 0; nt < 8; nt++) {
                const int n = nt * 8 + g;
                uint32_t bH[2] = { kh[n * 36 + co], kh[n * 36 + co + 4] };
                uint32_t bL[2] = { kl[n * 36 + co], kl[n * 36 + co + 4] };
                mma_bf16(s[nt], qH[ks], bL);
                mma_bf16(s[nt], qL[ks], bH);
                mma_bf16(s[nt], qH[ks], bH);
            }
        }

        // register softmax: rows g (s[][0..1]) and g+8 (s[][2..3])
        {
            float mx0 = -INFINITY, mx1 = -INFINITY;
#pragma unroll
            for (int nt = 0; nt < 8; nt++) {
                mx0 = fmaxf(mx0, fmaxf(s[nt][0], s[nt][1]));
                mx1 = fmaxf(mx1, fmaxf(s[nt][2], s[nt][3]));
            }
            mx0 = fmaxf(mx0, __shfl_xor_sync(0xffffffffu, mx0, 1));
            mx0 = fmaxf(mx0, __shfl_xor_sync(0xffffffffu, mx0, 2));
            mx1 = fmaxf(mx1, __shfl_xor_sync(0xffffffffu, mx1, 1));
            mx1 = fmaxf(mx1, __shfl_xor_sync(0xffffffffu, mx1, 2));
            const float m0n = fmaxf(m0, mx0);
            const float m1n = fmaxf(m1, mx1);
            const float fr0 = __expf(m0 - m0n);
            const float fr1 = __expf(m1 - m1n);
            m0 = m0n; m1 = m1n;
            float sum0 = 0.0f, sum1 = 0.0f;
#pragma unroll
            for (int nt = 0; nt < 8; nt++) {
                s[nt][0] = __expf(s[nt][0] - m0n);
                s[nt][1] = __expf(s[nt][1] - m0n);
                s[nt][2] = __expf(s[nt][2] - m1n);
                s[nt][3] = __expf(s[nt][3] - m1n);
                sum0 += s[nt][0] + s[nt][1];
                sum1 += s[nt][2] + s[nt][3];
            }
            sum0 += __shfl_xor_sync(0xffffffffu, sum0, 1);
            sum0 += __shfl_xor_sync(0xffffffffu, sum0, 2);
            sum1 += __shfl_xor_sync(0xffffffffu, sum1, 1);
            sum1 += __shfl_xor_sync(0xffffffffu, sum1, 2);
            l0 = l0 * fr0 + sum0;
            l1 = l1 * fr1 + sum1;
#pragma unroll
            for (int nt = 0; nt < 8; nt++) {
                o[nt][0] *= fr0; o[nt][1] *= fr0;
                o[nt][2] *= fr1; o[nt][3] *= fr1;
            }
        }

        // O += P @ V (bf16x3)
#pragma unroll
        for (int ks2 = 0; ks2 < 4; ks2++) {
            const int nt0 = 2 * ks2, nt1 = 2 * ks2 + 1;
            uint32_t aH[4], aL[4];
            split2(s[nt0][0], s[nt0][1], aH[0], aL[0]);
            split2(s[nt0][2], s[nt0][3], aH[1], aL[1]);
            split2(s[nt1][0], s[nt1][1], aH[2], aL[2]);
            split2(s[nt1][2], s[nt1][3], aH[3], aL[3]);
            const int co = ks2 * 8 + tg;
#pragma unroll
            for (int nt = 0; nt < 8; nt++) {
                const int d = nt * 8 + g;
                uint32_t bH[2] = { vh[co * 72 + d], vh[(co + 4) * 72 + d] };
                uint32_t bL[2] = { vl[co * 72 + d], vl[(co + 4) * 72 + d] };
                mma_bf16(o[nt], aH, bL);
                mma_bf16(o[nt], aL, bH);
                mma_bf16(o[nt], aH, bH);
            }
        }
        __syncthreads();
    }

    // normalize and write ctx
    {
        const float i0 = 1.0f / l0;
        const float i1 = 1.0f / l1;
        const long r0g = (long)(b * SS + q0 + wm + g) * DD + h * DH;
        const long r1g = (long)(b * SS + q0 + wm + g + 8) * DD + h * DH;
#pragma unroll
        for (int nt = 0; nt < 8; nt++) {
            const int dcol = nt * 8 + 2 * tg;
            float2 w0, w1;
            w0.x = o[nt][0] * i0; w0.y = o[nt][1] * i0;
            w1.x = o[nt][2] * i1; w1.y = o[nt][3] * i1;
            *reinterpret_cast<float2*>(&g_ctx[r0g + dcol]) = w0;
            *reinterpret_cast<float2*>(&g_ctx[r1g + dcol]) = w1;
        }
    }
}

// ---------------------------------------------------------------------------
// Launch
// ---------------------------------------------------------------------------
extern "C" void kernel_launch(void* const* d_in, const int* in_sizes, int n_in,
                              void* d_out, int out_size)
{
    const float* x  = (const float*)d_in[0];
    const float* Wq = (const float*)d_in[1];
    const float* bq = (const float*)d_in[2];
    const float* Wk = (const float*)d_in[3];
    const float* bk = (const float*)d_in[4];
    const float* Wv = (const float*)d_in[5];
    const float* bv = (const float*)d_in[6];
    const float* Wo = (const float*)d_in[7];
    const float* bo = (const float*)d_in[8];
    float* out = (float*)d_out;

    void *pv, *pctx, *pqh, *pql, *pkh, *pkl;
    cudaGetSymbolAddress(&pv,   g_v);
    cudaGetSymbolAddress(&pctx, g_ctx);
    cudaGetSymbolAddress(&pqh,  g_qh);
    cudaGetSymbolAddress(&pql,  g_ql);
    cudaGetSymbolAddress(&pkh,  g_kh);
    cudaGetSymbolAddress(&pkl,  g_kl);

    cudaFuncSetAttribute(attn_kernel,
                         cudaFuncAttributeMaxDynamicSharedMemorySize, ATT_SMEM);

    // fused QKV projection: z=0 -> Q (split), z=1 -> K (split), z=2 -> V (float)
    GemmArgs qkv;
    qkv.W[0] = Wq;  qkv.W[1] = Wk;  qkv.W[2] = Wv;
    qkv.bias[0] = bq; qkv.bias[1] = bk; qkv.bias[2] = bv;
    qkv.Cf[0] = nullptr;         qkv.Ch[0] = (uint32_t*)pqh; qkv.Cl[0] = (uint32_t*)pql;
    qkv.Cf[1] = nullptr;         qkv.Ch[1] = (uint32_t*)pkh; qkv.Cl[1] = (uint32_t*)pkl;
    qkv.Cf[2] = (float*)pv;      qkv.Ch[2] = nullptr;        qkv.Cl[2] = nullptr;
    gemm_bf16_kernel<<<dim3(DD / 128, MM / 128, 3), 256>>>(x, qkv);

    split_vt_kernel<<<MM * DP / 256, 256>>>();

    dim3 agrid(SS / 128, BB * HH);    // (16, 24)
    attn_kernel<<<agrid, 256, ATT_SMEM>>>();

    GemmArgs oarg;
    oarg.W[0] = Wo; oarg.bias[0] = bo;
    oarg.Cf[0] = out; oarg.Ch[0] = nullptr; oarg.Cl[0] = nullptr;
    oarg.W[1] = Wo; oarg.bias[1] = bo; oarg.Cf[1] = nullptr; oarg.Ch[1] = nullptr; oarg.Cl[1] = nullptr;
    oarg.W[2] = Wo; oarg.bias[2] = bo; oarg.Cf[2] = nullptr; oarg.Ch[2] = nullptr; oarg.Cl[2] = nullptr;
    gemm_bf16_kernel<<<dim3(DD / 128, MM / 128, 1), 256>>>((const float*)pctx, oarg);
}

// round 14
// speedup vs baseline: 3.2221x; 1.1365x over previous
#include <cuda_runtime.h>
#include <cuda_fp16.h>
#include <math.h>
#include <stdint.h>

#define BB 2
#define SS 2048
#define DD 768
#define HH 12
#define DH 64
#define MM (BB*SS)
#define DP (DD/2)     // 384 u32 pairs per row

// scratch (no allocations allowed — __device__ globals are the sanctioned path)
__device__ float g_v[MM*DD];
__device__ float g_ctx[MM*DD];
// packed fp16 hi/lo splits
__device__ uint32_t g_qh[MM*DP];
__device__ uint32_t g_ql[MM*DP];
__device__ uint32_t g_kh[MM*DP];
__device__ uint32_t g_kl[MM*DP];
__device__ uint32_t g_vth[MM*DP];   // V transposed: [(b*HH+h)*1024 + kp][d]
__device__ uint32_t g_vtl[MM*DP];

__device__ __forceinline__ void mma_f16(float* d,
                                        const uint32_t* a,
                                        const uint32_t* b) {
    asm volatile(
        "mma.sync.aligned.m16n8k16.row.col.f32.f16.f16.f32 "
        "{%0,%1,%2,%3}, {%4,%5,%6,%7}, {%8,%9}, {%0,%1,%2,%3};"
        : "+f"(d[0]), "+f"(d[1]), "+f"(d[2]), "+f"(d[3])
        : "r"(a[0]), "r"(a[1]), "r"(a[2]), "r"(a[3]),
          "r"(b[0]), "r"(b[1]));
}

// pack two floats into one fp16x2 (a -> low half, b -> high half)
__device__ __forceinline__ uint32_t pack2h(float a, float b) {
    uint32_t r;
    asm("cvt.rn.f16x2.f32 %0, %1, %2;" : "=r"(r) : "f"(b), "f"(a));
    return r;
}

// split (a,b) into packed fp16 hi-pair and lo-pair (low half = first element)
__device__ __forceinline__ void split2h(float a, float b,
                                        uint32_t& hi, uint32_t& lo) {
    __half ah = __float2half_rn(a);
    __half bh = __float2half_rn(b);
    hi = (uint32_t)__half_as_ushort(ah) |
         ((uint32_t)__half_as_ushort(bh) << 16);
    lo = pack2h(a - __half2float(ah), b - __half2float(bh));
}

__device__ __forceinline__ void cp16(uint32_t saddr, const void* gaddr) {
    asm volatile("cp.async.ca.shared.global [%0], [%1], 16;"
                 :: "r"(saddr), "l"(gaddr));
}
#define CP_COMMIT() asm volatile("cp.async.commit_group;" ::: "memory")
#define CP_WAIT1()  asm volatile("cp.async.wait_group 1;" ::: "memory")
#define CP_WAIT0()  asm volatile("cp.async.wait_group 0;" ::: "memory")

// ---------------------------------------------------------------------------
// fp16x2 (3-term) mma.sync GEMM with selectable epilogue.
// grid.z selects weight/bias/output set (fused QKV in one launch).
// BM=BN=128, BK=16, 256 threads, warp tile 64x32.
// ---------------------------------------------------------------------------
struct GemmArgs {
    const float* W[3];
    const float* bias[3];
    float*    Cf[3];
    uint32_t* Ch[3];
    uint32_t* Cl[3];
};

#define AST 9      // A smem u32 stride
#define BST 136    // B smem u32 stride

__global__ void __launch_bounds__(256)
gemm_f16_kernel(const float* __restrict__ A, GemmArgs args)
{
    __shared__ uint32_t AsH[128 * AST];
    __shared__ uint32_t AsL[128 * AST];
    __shared__ uint32_t BsH[8 * BST];
    __shared__ uint32_t BsL[8 * BST];
    __shared__ float sbias[128];

    const int z = blockIdx.z;
    const float* __restrict__ W    = args.W[z];
    const float* __restrict__ bias = args.bias[z];
    float*    Cf = args.Cf[z];
    uint32_t* Ch = args.Ch[z];
    uint32_t* Cl = args.Cl[z];

    const int tid  = threadIdx.x;
    const int warp = tid >> 5;
    const int lane = tid & 31;
    const int g    = lane >> 2;
    const int tg   = lane & 3;
    const int wm   = warp >> 2;
    const int wn   = warp & 3;
    const int m0   = blockIdx.y * 128;
    const int n0   = blockIdx.x * 128;

    if (tid < 128) sbias[tid] = bias[n0 + tid];

    const int ar0 = tid >> 2;
    const int aq0 = tid & 3;
    const int ar1 = (tid + 256) >> 2;
    const int aq1 = (tid + 256) & 3;
    const int bkp = tid >> 5;
    const int bnq = (tid & 31) << 2;

    float acc[4][4][4];
#pragma unroll
    for (int i = 0; i < 4; i++)
#pragma unroll
        for (int j = 0; j < 4; j++)
#pragma unroll
            for (int q = 0; q < 4; q++) acc[i][j][q] = 0.0f;

    float4 ra0, ra1, rb0, rb1;

    ra0 = *reinterpret_cast<const float4*>(&A[(long)(m0 + ar0) * DD + aq0 * 4]);
    ra1 = *reinterpret_cast<const float4*>(&A[(long)(m0 + ar1) * DD + aq1 * 4]);
    rb0 = *reinterpret_cast<const float4*>(&W[(long)(2 * bkp) * DD + n0 + bnq]);
    rb1 = *reinterpret_cast<const float4*>(&W[(long)(2 * bkp + 1) * DD + n0 + bnq]);

#define STORE_TILES() do {                                                   \
    split2h(ra0.x, ra0.y, AsH[ar0 * AST + aq0 * 2],     AsL[ar0 * AST + aq0 * 2]); \
    split2h(ra0.z, ra0.w, AsH[ar0 * AST + aq0 * 2 + 1], AsL[ar0 * AST + aq0 * 2 + 1]); \
    split2h(ra1.x, ra1.y, AsH[ar1 * AST + aq1 * 2],     AsL[ar1 * AST + aq1 * 2]); \
    split2h(ra1.z, ra1.w, AsH[ar1 * AST + aq1 * 2 + 1], AsL[ar1 * AST + aq1 * 2 + 1]); \
    split2h(rb0.x, rb1.x, BsH[bkp * BST + bnq],     BsL[bkp * BST + bnq]);     \
    split2h(rb0.y, rb1.y, BsH[bkp * BST + bnq + 1], BsL[bkp * BST + bnq + 1]); \
    split2h(rb0.z, rb1.z, BsH[bkp * BST + bnq + 2], BsL[bkp * BST + bnq + 2]); \
    split2h(rb0.w, rb1.w, BsH[bkp * BST + bnq + 3], BsL[bkp * BST + bnq + 3]); \
} while (0)

    STORE_TILES();
    __syncthreads();

    const int NITER = DD / 16;   // 48
    for (int it = 0; it < NITER; it++) {
        if (it + 1 < NITER) {
            const int k0 = (it + 1) * 16;
            ra0 = *reinterpret_cast<const float4*>(&A[(long)(m0 + ar0) * DD + k0 + aq0 * 4]);
            ra1 = *reinterpret_cast<const float4*>(&A[(long)(m0 + ar1) * DD + k0 + aq1 * 4]);
            rb0 = *reinterpret_cast<const float4*>(&W[(long)(k0 + 2 * bkp) * DD + n0 + bnq]);
            rb1 = *reinterpret_cast<const float4*>(&W[(long)(k0 + 2 * bkp + 1) * DD + n0 + bnq]);
        }

        uint32_t afH[4][4], afL[4][4], bfH[4][2], bfL[4][2];
#pragma unroll
        for (int mi = 0; mi < 4; mi++) {
            const int r = wm * 64 + mi * 16 + g;
            afH[mi][0] = AsH[r * AST + tg];
            afH[mi][1] = AsH[(r + 8) * AST + tg];
            afH[mi][2] = AsH[r * AST + tg + 4];
            afH[mi][3] = AsH[(r + 8) * AST + tg + 4];
            afL[mi][0] = AsL[r * AST + tg];
            afL[mi][1] = AsL[(r + 8) * AST + tg];
            afL[mi][2] = AsL[r * AST + tg + 4];
            afL[mi][3] = AsL[(r + 8) * AST + tg + 4];
        }
#pragma unroll
        for (int ni = 0; ni < 4; ni++) {
            const int c = wn * 32 + ni * 8 + g;
            bfH[ni][0] = BsH[tg * BST + c];
            bfH[ni][1] = BsH[(tg + 4) * BST + c];
            bfL[ni][0] = BsL[tg * BST + c];
            bfL[ni][1] = BsL[(tg + 4) * BST + c];
        }
#pragma unroll
        for (int mi = 0; mi < 4; mi++)
#pragma unroll
            for (int ni = 0; ni < 4; ni++) {
                mma_f16(acc[mi][ni], afH[mi], bfL[ni]);
                mma_f16(acc[mi][ni], afL[mi], bfH[ni]);
                mma_f16(acc[mi][ni], afH[mi], bfH[ni]);
            }
        __syncthreads();
        if (it + 1 < NITER) {
            STORE_TILES();
            __syncthreads();
        }
    }

    // epilogue
    const int rr = lane >> 2;
    const int cc = (lane & 3) * 2;
    if (Ch) {
        // packed fp16 hi/lo output (Q/K path)
#pragma unroll
        for (int mi = 0; mi < 4; mi++) {
#pragma unroll
            for (int ni = 0; ni < 4; ni++) {
                const int col = wn * 32 + ni * 8 + cc;
                const int row = m0 + wm * 64 + mi * 16 + rr;
                const int pc  = (n0 + col) >> 1;
                const float v0 = acc[mi][ni][0] + sbias[col];
                const float v1 = acc[mi][ni][1] + sbias[col + 1];
                const float v2 = acc[mi][ni][2] + sbias[col];
                const float v3 = acc[mi][ni][3] + sbias[col + 1];
                uint32_t hi, lo;
                split2h(v0, v1, hi, lo);
                Ch[(long)row * DP + pc] = hi;
                Cl[(long)row * DP + pc] = lo;
                split2h(v2, v3, hi, lo);
                Ch[(long)(row + 8) * DP + pc] = hi;
                Cl[(long)(row + 8) * DP + pc] = lo;
            }
        }
    } else {
        // float output (V and O paths)
#pragma unroll
        for (int mi = 0; mi < 4; mi++) {
#pragma unroll
            for (int ni = 0; ni < 4; ni++) {
                const int col = wn * 32 + ni * 8 + cc;
                const int row = m0 + wm * 64 + mi * 16 + rr;
                float2 o0, o1;
                o0.x = acc[mi][ni][0] + sbias[col];
                o0.y = acc[mi][ni][1] + sbias[col + 1];
                o1.x = acc[mi][ni][2] + sbias[col];
                o1.y = acc[mi][ni][3] + sbias[col + 1];
                *reinterpret_cast<float2*>(&Cf[(long)row * DD + n0 + col]) = o0;
                *reinterpret_cast<float2*>(&Cf[(long)(row + 8) * DD + n0 + col]) = o1;
            }
        }
    }
}

// ---------------------------------------------------------------------------
// Pre-pass: V transposed-packed fp16 split.
// ---------------------------------------------------------------------------
__global__ void __launch_bounds__(256)
split_vt_kernel()
{
    const int idx = blockIdx.x * 256 + threadIdx.x;   // < BB*HH*(SS/2)*DH
    const int d  = idx & 63;
    const int kp = (idx >> 6) & 1023;
    const int bh = idx >> 16;
    const int b  = bh / HH;
    const int h  = bh % HH;
    const long base = (long)(b * SS + 2 * kp) * DD + h * DH + d;
    uint32_t hi, lo;
    split2h(g_v[base], g_v[base + DD], hi, lo);
    g_vth[idx] = hi;
    g_vtl[idx] = lo;
}

// ---------------------------------------------------------------------------
// Flash attention: fp16 mma.sync, register softmax, cp.async double-buffer.
// S = QK^T via fp16x2 3-term; PV via single-fp16 P x (Vh + Vl) = 2 MMAs.
// CTA = 128 queries x one (b,h); 8 warps, each owns m16 x full n64.
// K tiles: [key(64)][dpair(32)] stride 36; V tiles: [kp(32)][d(64)] stride 72.
// ---------------------------------------------------------------------------
#define KTILE 2304                      // 64*36 == 32*72 u32 per array per stage
#define ATT_SMEM (8 * KTILE * 4)        // 73728 B
#define NT (SS/64)                      // 32

__global__ void __launch_bounds__(256)
attn_kernel()
{
    extern __shared__ uint32_t smatt[];
    uint32_t* sKh = smatt;
    uint32_t* sKl = smatt + 2 * KTILE;
    uint32_t* sVh = smatt + 4 * KTILE;
    uint32_t* sVl = smatt + 6 * KTILE;

    const uint32_t aKh = (uint32_t)__cvta_generic_to_shared(sKh);
    const uint32_t aKl = (uint32_t)__cvta_generic_to_shared(sKl);
    const uint32_t aVh = (uint32_t)__cvta_generic_to_shared(sVh);
    const uint32_t aVl = (uint32_t)__cvta_generic_to_shared(sVl);

    const int tid  = threadIdx.x;
    const int warp = tid >> 5;
    const int lane = tid & 31;
    const int g    = lane >> 2;
    const int tg   = lane & 3;
    const int wm   = warp * 16;
    const int bh   = blockIdx.y;
    const int b    = bh / HH;
    const int h    = bh % HH;
    const int q0   = blockIdx.x * 128;

    const uint32_t* khg = &g_kh[(long)(b * SS) * DP + h * 32];
    const uint32_t* klg = &g_kl[(long)(b * SS) * DP + h * 32];
    const uint32_t* vhg = &g_vth[(long)(b * HH + h) * (SS / 2) * 64];
    const uint32_t* vlg = &g_vtl[(long)(b * HH + h) * (SS / 2) * 64];

    const int kr0 = tid >> 3,            kq0 = (tid & 7) * 4;
    const int kr1 = (tid + 256) >> 3,    kq1 = ((tid + 256) & 7) * 4;
    const int vr0 = tid >> 4,            vq0 = (tid & 15) * 4;
    const int vr1 = (tid + 256) >> 4,    vq1 = ((tid + 256) & 15) * 4;

#define ISSUE_STAGE(kt, st) do {                                             \
    const int _k0 = (kt) * 64;                                               \
    const uint32_t _so = (uint32_t)(st) * KTILE * 4;                         \
    cp16(aKh + _so + (kr0 * 36 + kq0) * 4, khg + (long)(_k0 + kr0) * DP + kq0); \
    cp16(aKh + _so + (kr1 * 36 + kq1) * 4, khg + (long)(_k0 + kr1) * DP + kq1); \
    cp16(aKl + _so + (kr0 * 36 + kq0) * 4, klg + (long)(_k0 + kr0) * DP + kq0); \
    cp16(aKl + _so + (kr1 * 36 + kq1) * 4, klg + (long)(_k0 + kr1) * DP + kq1); \
    cp16(aVh + _so + (vr0 * 72 + vq0) * 4, vhg + (long)(_k0 / 2 + vr0) * 64 + vq0); \
    cp16(aVh + _so + (vr1 * 72 + vq1) * 4, vhg + (long)(_k0 / 2 + vr1) * 64 + vq1); \
    cp16(aVl + _so + (vr0 * 72 + vq0) * 4, vlg + (long)(_k0 / 2 + vr0) * 64 + vq0); \
    cp16(aVl + _so + (vr1 * 72 + vq1) * 4, vlg + (long)(_k0 / 2 + vr1) * 64 + vq1); \
    CP_COMMIT();                                                             \
} while (0)

    // Q fragments to registers (once)
    uint32_t qH[4][4], qL[4][4];
    {
        const uint32_t* qh = &g_qh[(long)(b * SS + q0 + wm) * DP + h * 32];
        const uint32_t* ql = &g_ql[(long)(b * SS + q0 + wm) * DP + h * 32];
#pragma unroll
        for (int ks = 0; ks < 4; ks++) {
            const int c = ks * 8 + tg;
            qH[ks][0] = qh[g * DP + c];
            qH[ks][1] = qh[(g + 8) * DP + c];
            qH[ks][2] = qh[g * DP + c + 4];
            qH[ks][3] = qh[(g + 8) * DP + c + 4];
            qL[ks][0] = ql[g * DP + c];
            qL[ks][1] = ql[(g + 8) * DP + c];
            qL[ks][2] = ql[g * DP + c + 4];
            qL[ks][3] = ql[(g + 8) * DP + c + 4];
        }
    }

    float m0 = -INFINITY, m1 = -INFINITY, l0 = 0.0f, l1 = 0.0f;
    float o[8][4];
#pragma unroll
    for (int nt = 0; nt < 8; nt++)
#pragma unroll
        for (int q = 0; q < 4; q++) o[nt][q] = 0.0f;

    ISSUE_STAGE(0, 0);

    for (int kt = 0; kt < NT; kt++) {
        const int st = kt & 1;
        if (kt + 1 < NT) {
            ISSUE_STAGE(kt + 1, st ^ 1);
            CP_WAIT1();
        } else {
            CP_WAIT0();
        }
        __syncthreads();

        const uint32_t* kh = sKh + st * KTILE;
        const uint32_t* kl = sKl + st * KTILE;
        const uint32_t* vh = sVh + st * KTILE;
        const uint32_t* vl = sVl + st * KTILE;

        // S = Q @ K^T (fp16x2, 3 terms)
        float s[8][4];
#pragma unroll
        for (int nt = 0; nt < 8; nt++)
#pragma unroll
            for (int q = 0; q < 4; q++) s[nt][q] = 0.0f;
#pragma unroll
        for (int ks = 0; ks < 4; ks++) {
            const int co = ks * 8 + tg;
#pragma unroll
            for (int nt = 0; nt < 8; nt++) {
                const int n = nt * 8 + g;
                uint32_t bH[2] = { kh[n * 36 + co], kh[n * 36 + co + 4] };
                uint32_t bL[2] = { kl[n * 36 + co], kl[n * 36 + co + 4] };
                mma_f16(s[nt], qH[ks], bL);
                mma_f16(s[nt], qL[ks], bH);
                mma_f16(s[nt], qH[ks], bH);
            }
        }

        // register softmax: rows g (s[][0..1]) and g+8 (s[][2..3])
        {
            float mx0 = -INFINITY, mx1 = -INFINITY;
#pragma unroll
            for (int nt = 0; nt < 8; nt++) {
                mx0 = fmaxf(mx0, fmaxf(s[nt][0], s[nt][1]));
                mx1 = fmaxf(mx1, fmaxf(s[nt][2], s[nt][3]));
            }
            mx0 = fmaxf(mx0, __shfl_xor_sync(0xffffffffu, mx0, 1));
            mx0 = fmaxf(mx0, __shfl_xor_sync(0xffffffffu, mx0, 2));
            mx1 = fmaxf(mx1, __shfl_xor_sync(0xffffffffu, mx1, 1));
            mx1 = fmaxf(mx1, __shfl_xor_sync(0xffffffffu, mx1, 2));
            const float m0n = fmaxf(m0, mx0);
            const float m1n = fmaxf(m1, mx1);
            const float fr0 = __expf(m0 - m0n);
            const float fr1 = __expf(m1 - m1n);
            m0 = m0n; m1 = m1n;
            float sum0 = 0.0f, sum1 = 0.0f;
#pragma unroll
            for (int nt = 0; nt < 8; nt++) {
                s[nt][0] = __expf(s[nt][0] - m0n);
                s[nt][1] = __expf(s[nt][1] - m0n);
                s[nt][2] = __expf(s[nt][2] - m1n);
                s[nt][3] = __expf(s[nt][3] - m1n);
                sum0 += s[nt][0] + s[nt][1];
                sum1 += s[nt][2] + s[nt][3];
            }
            sum0 += __shfl_xor_sync(0xffffffffu, sum0, 1);
            sum0 += __shfl_xor_sync(0xffffffffu, sum0, 2);
            sum1 += __shfl_xor_sync(0xffffffffu, sum1, 1);
            sum1 += __shfl_xor_sync(0xffffffffu, sum1, 2);
            l0 = l0 * fr0 + sum0;
            l1 = l1 * fr1 + sum1;
#pragma unroll
            for (int nt = 0; nt < 8; nt++) {
                o[nt][0] *= fr0; o[nt][1] *= fr0;
                o[nt][2] *= fr1; o[nt][3] *= fr1;
            }
        }

        // O += P @ V; P single fp16, V hi+lo (2 MMAs)
#pragma unroll
        for (int ks2 = 0; ks2 < 4; ks2++) {
            const int nt0 = 2 * ks2, nt1 = 2 * ks2 + 1;
            uint32_t aP[4];
            aP[0] = pack2h(s[nt0][0], s[nt0][1]);
            aP[1] = pack2h(s[nt0][2], s[nt0][3]);
            aP[2] = pack2h(s[nt1][0], s[nt1][1]);
            aP[3] = pack2h(s[nt1][2], s[nt1][3]);
            const int co = ks2 * 8 + tg;
#pragma unroll
            for (int nt = 0; nt < 8; nt++) {
                const int d = nt * 8 + g;
                uint32_t bH[2] = { vh[co * 72 + d], vh[(co + 4) * 72 + d] };
                uint32_t bL[2] = { vl[co * 72 + d], vl[(co + 4) * 72 + d] };
                mma_f16(o[nt], aP, bL);
                mma_f16(o[nt], aP, bH);
            }
        }
        __syncthreads();
    }

    // normalize and write ctx
    {
        const float i0 = 1.0f / l0;
        const float i1 = 1.0f / l1;
        const long r0g = (long)(b * SS + q0 + wm + g) * DD + h * DH;
        const long r1g = (long)(b * SS + q0 + wm + g + 8) * DD + h * DH;
#pragma unroll
        for (int nt = 0; nt < 8; nt++) {
            const int dcol = nt * 8 + 2 * tg;
            float2 w0, w1;
            w0.x = o[nt][0] * i0; w0.y = o[nt][1] * i0;
            w1.x = o[nt][2] * i1; w1.y = o[nt][3] * i1;
            *reinterpret_cast<float2*>(&g_ctx[r0g + dcol]) = w0;
            *reinterpret_cast<float2*>(&g_ctx[r1g + dcol]) = w1;
        }
    }
}

// ---------------------------------------------------------------------------
// Launch
// ---------------------------------------------------------------------------
extern "C" void kernel_launch(void* const* d_in, const int* in_sizes, int n_in,
                              void* d_out, int out_size)
{
    const float* x  = (const float*)d_in[0];
    const float* Wq = (const float*)d_in[1];
    const float* bq = (const float*)d_in[2];
    const float* Wk = (const float*)d_in[3];
    const float* bk = (const float*)d_in[4];
    const float* Wv = (const float*)d_in[5];
    const float* bv = (const float*)d_in[6];
    const float* Wo = (const float*)d_in[7];
    const float* bo = (const float*)d_in[8];
    float* out = (float*)d_out;

    void *pv, *pctx, *pqh, *pql, *pkh, *pkl;
    cudaGetSymbolAddress(&pv,   g_v);
    cudaGetSymbolAddress(&pctx, g_ctx);
    cudaGetSymbolAddress(&pqh,  g_qh);
    cudaGetSymbolAddress(&pql,  g_ql);
    cudaGetSymbolAddress(&pkh,  g_kh);
    cudaGetSymbolAddress(&pkl,  g_kl);

    cudaFuncSetAttribute(attn_kernel,
                         cudaFuncAttributeMaxDynamicSharedMemorySize, ATT_SMEM);

    // fused QKV projection: z=0 -> Q (split), z=1 -> K (split), z=2 -> V (float)
    GemmArgs qkv;
    qkv.W[0] = Wq;  qkv.W[1] = Wk;  qkv.W[2] = Wv;
    qkv.bias[0] = bq; qkv.bias[1] = bk; qkv.bias[2] = bv;
    qkv.Cf[0] = nullptr;         qkv.Ch[0] = (uint32_t*)pqh; qkv.Cl[0] = (uint32_t*)pql;
    qkv.Cf[1] = nullptr;         qkv.Ch[1] = (uint32_t*)pkh; qkv.Cl[1] = (uint32_t*)pkl;
    qkv.Cf[2] = (float*)pv;      qkv.Ch[2] = nullptr;        qkv.Cl[2] = nullptr;
    gemm_f16_kernel<<<dim3(DD / 128, MM / 128, 3), 256>>>(x, qkv);

    split_vt_kernel<<<MM * DP / 256, 256>>>();

    dim3 agrid(SS / 128, BB * HH);    // (16, 24)
    attn_kernel<<<agrid, 256, ATT_SMEM>>>();

    GemmArgs oarg;
    oarg.W[0] = Wo; oarg.bias[0] = bo;
    oarg.Cf[0] = out; oarg.Ch[0] = nullptr; oarg.Cl[0] = nullptr;
    oarg.W[1] = Wo; oarg.bias[1] = bo; oarg.Cf[1] = nullptr; oarg.Ch[1] = nullptr; oarg.Cl[1] = nullptr;
    oarg.W[2] = Wo; oarg.bias[2] = bo; oarg.Cf[2] = nullptr; oarg.Ch[2] = nullptr; oarg.Cl[2] = nullptr;
    gemm_f16_kernel<<<dim3(DD / 128, MM / 128, 1), 256>>>((const float*)pctx, oarg);
}